// round 9
// baseline (speedup 1.0000x reference)
#include <cuda_runtime.h>
#include <cuda_fp16.h>

#define N_NODES 16384
#define SZ 128
typedef unsigned long long ull;

__device__ __forceinline__ ull ffma2(ull a, ull b, ull c) {
    ull d;
    asm("fma.rn.f32x2 %0, %1, %2, %3;" : "=l"(d) : "l"(a), "l"(b), "l"(c));
    return d;
}
__device__ __forceinline__ ull pack2(float x, float y) {
    ull d;
    asm("mov.b64 %0, {%1, %2};" : "=l"(d) : "f"(x), "f"(y));
    return d;
}
__device__ __forceinline__ float2 unpack2(ull v) {
    float2 r;
    asm("mov.b64 {%0, %1}, %2;" : "=f"(r.x), "=f"(r.y) : "l"(v));
    return r;
}
__device__ __forceinline__ unsigned h2u(__half2 h) { return *(unsigned*)&h; }

// ---------------- scratch ----------------
__device__ float  g_h1[N_NODES * SZ];
__device__ float  g_h2[N_NODES * SZ];
__device__ float  g_msg[N_NODES * SZ];
__device__ float  g_q[N_NODES * SZ];
__device__ __half g_mk[N_NODES * SZ];
__device__ __half g_mv[N_NODES * SZ];
__device__ float  g_att[N_NODES * SZ];

// ---------------- GEMM (R4-proven): BM=64, BN=128, BK=32, 256 thr, 8x4/thr -
template <int RELU_IN, int RELU_OUT, int HAS_BIAS, int HAS_ADD>
__global__ __launch_bounds__(256) void gemm128(
    const float* __restrict__ A, const float* __restrict__ W,
    const float* __restrict__ bias, const float* __restrict__ add,
    float* __restrict__ C)
{
    __shared__ float As[32 * 64];    // [k][row]
    __shared__ float Ws[32 * 128];   // [k][col]
    const int t = threadIdx.x;
    const int tx = t & 31;
    const int ty = t >> 5;
    const int row0 = blockIdx.x * 64;

    float acc[8][4];
#pragma unroll
    for (int r = 0; r < 8; r++)
#pragma unroll
        for (int c = 0; c < 4; c++) acc[r][c] = 0.0f;

    for (int kt = 0; kt < 4; kt++) {
        const int kk0 = kt * 32;
        __syncthreads();
#pragma unroll
        for (int i = 0; i < 2; i++) {
            int f = t + i * 256;
            int r = f >> 3, c4 = f & 7;
            float4 v = *(const float4*)(A + (row0 + r) * 128 + kk0 + c4 * 4);
            if (RELU_IN) {
                v.x = fmaxf(v.x, 0.f); v.y = fmaxf(v.y, 0.f);
                v.z = fmaxf(v.z, 0.f); v.w = fmaxf(v.w, 0.f);
            }
            As[(c4 * 4 + 0) * 64 + r] = v.x;
            As[(c4 * 4 + 1) * 64 + r] = v.y;
            As[(c4 * 4 + 2) * 64 + r] = v.z;
            As[(c4 * 4 + 3) * 64 + r] = v.w;
        }
#pragma unroll
        for (int i = 0; i < 4; i++) {
            int f = t + i * 256;
            int kr = f >> 5, c4 = f & 31;
            *(float4*)(Ws + kr * 128 + c4 * 4) =
                *(const float4*)(W + (kk0 + kr) * 128 + c4 * 4);
        }
        __syncthreads();
#pragma unroll
        for (int kk = 0; kk < 32; kk++) {
            float4 a0 = *(const float4*)(As + kk * 64 + ty * 8);
            float4 a1 = *(const float4*)(As + kk * 64 + ty * 8 + 4);
            float4 w  = *(const float4*)(Ws + kk * 128 + tx * 4);
            float ar[8] = {a0.x, a0.y, a0.z, a0.w, a1.x, a1.y, a1.z, a1.w};
#pragma unroll
            for (int r = 0; r < 8; r++) {
                acc[r][0] += ar[r] * w.x;
                acc[r][1] += ar[r] * w.y;
                acc[r][2] += ar[r] * w.z;
                acc[r][3] += ar[r] * w.w;
            }
        }
    }

    float4 bz = make_float4(0.f, 0.f, 0.f, 0.f);
    if (HAS_BIAS) bz = *(const float4*)(bias + tx * 4);
#pragma unroll
    for (int r = 0; r < 8; r++) {
        int gr = row0 + ty * 8 + r;
        float4 o;
        o.x = acc[r][0] + bz.x;
        o.y = acc[r][1] + bz.y;
        o.z = acc[r][2] + bz.z;
        o.w = acc[r][3] + bz.w;
        if (RELU_OUT) {
            o.x = fmaxf(o.x, 0.f); o.y = fmaxf(o.y, 0.f);
            o.z = fmaxf(o.z, 0.f); o.w = fmaxf(o.w, 0.f);
        }
        if (HAS_ADD) {
            float4 av = *(const float4*)(add + gr * 128 + tx * 4);
            o.x += av.x; o.y += av.y; o.z += av.z; o.w += av.w;
        }
        *(float4*)(C + gr * 128 + tx * 4) = o;
    }
}

// ------- fused h1 & q: h1 = relu(relu(F)@W1+b1), q = F@Wq+bq (F loaded once)
__global__ __launch_bounds__(256) void gemm_h1_q(
    const float* __restrict__ F, const float* __restrict__ W1g,
    const float* __restrict__ b1, const float* __restrict__ Wqg,
    const float* __restrict__ bq, float* __restrict__ H1,
    float* __restrict__ Q)
{
    __shared__ float AsR[32 * 64];   // relu(F), [k][row]
    __shared__ float AsN[32 * 64];   // raw F
    __shared__ float Ws1[32 * 128];
    __shared__ float Ws2[32 * 128];
    const int t = threadIdx.x;
    const int tx = t & 31;
    const int ty = t >> 5;
    const int row0 = blockIdx.x * 64;

    float a1[8][4], a2[8][4];
#pragma unroll
    for (int r = 0; r < 8; r++)
#pragma unroll
        for (int c = 0; c < 4; c++) { a1[r][c] = 0.f; a2[r][c] = 0.f; }

    for (int kt = 0; kt < 4; kt++) {
        const int kk0 = kt * 32;
        __syncthreads();
#pragma unroll
        for (int i = 0; i < 2; i++) {
            int f = t + i * 256;
            int r = f >> 3, c4 = f & 7;
            float4 v = *(const float4*)(F + (row0 + r) * 128 + kk0 + c4 * 4);
            AsN[(c4 * 4 + 0) * 64 + r] = v.x;
            AsN[(c4 * 4 + 1) * 64 + r] = v.y;
            AsN[(c4 * 4 + 2) * 64 + r] = v.z;
            AsN[(c4 * 4 + 3) * 64 + r] = v.w;
            AsR[(c4 * 4 + 0) * 64 + r] = fmaxf(v.x, 0.f);
            AsR[(c4 * 4 + 1) * 64 + r] = fmaxf(v.y, 0.f);
            AsR[(c4 * 4 + 2) * 64 + r] = fmaxf(v.z, 0.f);
            AsR[(c4 * 4 + 3) * 64 + r] = fmaxf(v.w, 0.f);
        }
#pragma unroll
        for (int i = 0; i < 4; i++) {
            int f = t + i * 256;
            int kr = f >> 5, c4 = f & 31;
            *(float4*)(Ws1 + kr * 128 + c4 * 4) =
                *(const float4*)(W1g + (kk0 + kr) * 128 + c4 * 4);
            *(float4*)(Ws2 + kr * 128 + c4 * 4) =
                *(const float4*)(Wqg + (kk0 + kr) * 128 + c4 * 4);
        }
        __syncthreads();
#pragma unroll
        for (int kk = 0; kk < 32; kk++) {
            float4 r0 = *(const float4*)(AsR + kk * 64 + ty * 8);
            float4 r1 = *(const float4*)(AsR + kk * 64 + ty * 8 + 4);
            float4 n0 = *(const float4*)(AsN + kk * 64 + ty * 8);
            float4 n1 = *(const float4*)(AsN + kk * 64 + ty * 8 + 4);
            float4 w1 = *(const float4*)(Ws1 + kk * 128 + tx * 4);
            float4 w2 = *(const float4*)(Ws2 + kk * 128 + tx * 4);
            float rr[8] = {r0.x, r0.y, r0.z, r0.w, r1.x, r1.y, r1.z, r1.w};
            float nn[8] = {n0.x, n0.y, n0.z, n0.w, n1.x, n1.y, n1.z, n1.w};
#pragma unroll
            for (int r = 0; r < 8; r++) {
                a1[r][0] += rr[r] * w1.x; a1[r][1] += rr[r] * w1.y;
                a1[r][2] += rr[r] * w1.z; a1[r][3] += rr[r] * w1.w;
                a2[r][0] += nn[r] * w2.x; a2[r][1] += nn[r] * w2.y;
                a2[r][2] += nn[r] * w2.z; a2[r][3] += nn[r] * w2.w;
            }
        }
    }

    float4 bz1 = *(const float4*)(b1 + tx * 4);
    float4 bzq = *(const float4*)(bq + tx * 4);
#pragma unroll
    for (int r = 0; r < 8; r++) {
        int gr = row0 + ty * 8 + r;
        float4 o1 = make_float4(fmaxf(a1[r][0] + bz1.x, 0.f),
                                fmaxf(a1[r][1] + bz1.y, 0.f),
                                fmaxf(a1[r][2] + bz1.z, 0.f),
                                fmaxf(a1[r][3] + bz1.w, 0.f));
        float4 oq = make_float4(a2[r][0] + bzq.x, a2[r][1] + bzq.y,
                                a2[r][2] + bzq.z, a2[r][3] + bzq.w);
        *(float4*)(H1 + gr * 128 + tx * 4) = o1;
        *(float4*)(Q + gr * 128 + tx * 4) = oq;
    }
}

// ---------------- dual GEMM -> fp16: mk = A@Wk[:128], mv = A@Wv[:128] ------
__global__ __launch_bounds__(256) void gemm128_dual_h(
    const float* __restrict__ A, const float* __restrict__ W1g,
    const float* __restrict__ W2g, __half* __restrict__ C1,
    __half* __restrict__ C2)
{
    __shared__ float As[32 * 64];
    __shared__ float Ws1[32 * 128];
    __shared__ float Ws2[32 * 128];
    const int t = threadIdx.x;
    const int tx = t & 31;
    const int ty = t >> 5;
    const int row0 = blockIdx.x * 64;

    float a1[8][4], a2[8][4];
#pragma unroll
    for (int r = 0; r < 8; r++)
#pragma unroll
        for (int c = 0; c < 4; c++) { a1[r][c] = 0.f; a2[r][c] = 0.f; }

    for (int kt = 0; kt < 4; kt++) {
        const int kk0 = kt * 32;
        __syncthreads();
#pragma unroll
        for (int i = 0; i < 2; i++) {
            int f = t + i * 256;
            int r = f >> 3, c4 = f & 7;
            float4 v = *(const float4*)(A + (row0 + r) * 128 + kk0 + c4 * 4);
            As[(c4 * 4 + 0) * 64 + r] = v.x;
            As[(c4 * 4 + 1) * 64 + r] = v.y;
            As[(c4 * 4 + 2) * 64 + r] = v.z;
            As[(c4 * 4 + 3) * 64 + r] = v.w;
        }
#pragma unroll
        for (int i = 0; i < 4; i++) {
            int f = t + i * 256;
            int kr = f >> 5, c4 = f & 31;
            *(float4*)(Ws1 + kr * 128 + c4 * 4) =
                *(const float4*)(W1g + (kk0 + kr) * 128 + c4 * 4);
            *(float4*)(Ws2 + kr * 128 + c4 * 4) =
                *(const float4*)(W2g + (kk0 + kr) * 128 + c4 * 4);
        }
        __syncthreads();
#pragma unroll
        for (int kk = 0; kk < 32; kk++) {
            float4 a0 = *(const float4*)(As + kk * 64 + ty * 8);
            float4 a1r = *(const float4*)(As + kk * 64 + ty * 8 + 4);
            float4 w1 = *(const float4*)(Ws1 + kk * 128 + tx * 4);
            float4 w2 = *(const float4*)(Ws2 + kk * 128 + tx * 4);
            float ar[8] = {a0.x, a0.y, a0.z, a0.w, a1r.x, a1r.y, a1r.z, a1r.w};
#pragma unroll
            for (int r = 0; r < 8; r++) {
                a1[r][0] += ar[r] * w1.x; a1[r][1] += ar[r] * w1.y;
                a1[r][2] += ar[r] * w1.z; a1[r][3] += ar[r] * w1.w;
                a2[r][0] += ar[r] * w2.x; a2[r][1] += ar[r] * w2.y;
                a2[r][2] += ar[r] * w2.z; a2[r][3] += ar[r] * w2.w;
            }
        }
    }
#pragma unroll
    for (int r = 0; r < 8; r++) {
        int gr = row0 + ty * 8 + r;
        uint2 o1, o2;
        o1.x = h2u(__float22half2_rn(make_float2(a1[r][0], a1[r][1])));
        o1.y = h2u(__float22half2_rn(make_float2(a1[r][2], a1[r][3])));
        o2.x = h2u(__float22half2_rn(make_float2(a2[r][0], a2[r][1])));
        o2.y = h2u(__float22half2_rn(make_float2(a2[r][2], a2[r][3])));
        *(uint2*)(C1 + (long)gr * 128 + tx * 4) = o1;
        *(uint2*)(C2 + (long)gr * 128 + tx * 4) = o2;
    }
}

// ---------------- attention: 1 warp/node, fp16 staging, 8.1KB smem/warp ----
struct __align__(16) WarpSmem {
    __half dist[32 * 36];  // [k][d] pad-36 halves (72B rows, 8B-aligned)
    __half seq[32 * 20];   // [k][s] pad-20 halves (40B rows)
    float ud_t[32 * 8];    // [d][h]  (transposed fold tables)
    float us_t[16 * 8];    // [s][h]
    float c0[8];
    float lgk[32 * 10];    // [k][h] pad-10
    float sd[8 * 32];
    float ss[8 * 16];
    int   jb[32];
};

__global__ __launch_bounds__(128, 7) void attn_kernel(
    const float* __restrict__ dist_g, const float* __restrict__ seq_g,
    const int* __restrict__ idx, const float* __restrict__ qg,
    const __half* __restrict__ mkh, const __half* __restrict__ mvh,
    const float* __restrict__ Wk, const float* __restrict__ bk,
    const float* __restrict__ Wv, const float* __restrict__ bv,
    float* __restrict__ att_out)
{
    __shared__ WarpSmem S[4];
    const int lane = threadIdx.x & 31;
    const int w = threadIdx.x >> 5;
    WarpSmem& s = S[w];
    const int n = blockIdx.x * 4 + w;

    // ---- Phase A: coalesced staging (fp32 global -> fp16 smem)
    const float4 qv = ((const float4*)(qg + (long)n * 128))[lane];
    s.jb[lane] = idx[n * 32 + lane];
    {
        const float4* dg = (const float4*)(dist_g + (long)n * 1024);
#pragma unroll
        for (int it = 0; it < 8; it++) {
            int i4 = it * 32 + lane;
            float4 v = dg[i4];
            uint2 h;
            h.x = h2u(__float22half2_rn(make_float2(v.x, v.y)));
            h.y = h2u(__float22half2_rn(make_float2(v.z, v.w)));
            *(uint2*)(s.dist + (i4 >> 3) * 36 + (i4 & 7) * 4) = h;
        }
        const float4* sg = (const float4*)(seq_g + (long)n * 512);
#pragma unroll
        for (int it = 0; it < 4; it++) {
            int i4 = it * 32 + lane;
            float4 v = sg[i4];
            uint2 h;
            h.x = h2u(__float22half2_rn(make_float2(v.x, v.y)));
            h.y = h2u(__float22half2_rn(make_float2(v.z, v.w)));
            *(uint2*)(s.seq + (i4 >> 2) * 20 + (i4 & 3) * 4) = h;
        }
    }
    __syncwarp();

    // ---- Phase B: folds into TRANSPOSED tables ud_t[d][h], us_t[s][h]
    const int h4 = lane >> 2;
#pragma unroll 8
    for (int r = 0; r < 48; r++) {
        float4 wv = *(const float4*)(Wk + (long)(128 + r) * 128 + lane * 4);
        float p = wv.x * qv.x + wv.y * qv.y + wv.z * qv.z + wv.w * qv.w;
        p += __shfl_xor_sync(~0u, p, 1);
        p += __shfl_xor_sync(~0u, p, 2);
        if ((lane & 3) == 0) {
            if (r < 32) s.ud_t[r * 8 + h4] = p;
            else        s.us_t[(r - 32) * 8 + h4] = p;
        }
    }
    {
        float4 wv = *(const float4*)(bk + lane * 4);
        float p = wv.x * qv.x + wv.y * qv.y + wv.z * qv.z + wv.w * qv.w;
        p += __shfl_xor_sync(~0u, p, 1);
        p += __shfl_xor_sync(~0u, p, 2);
        if ((lane & 3) == 0) s.c0[h4] = p;
    }
    __syncwarp();

    // ---- Phase C1: q . mk[jb[k]] — fp16 rows, 8B/lane coalesced
#pragma unroll 8
    for (int k = 0; k < 32; k++) {
        int j = s.jb[k];
        uint2 mr = *(const uint2*)(mkh + (long)j * 128 + lane * 4);
        float2 f0 = __half22float2(*(__half2*)&mr.x);
        float2 f1 = __half22float2(*(__half2*)&mr.y);
        float p = f0.x * qv.x + f0.y * qv.y + f1.x * qv.z + f1.y * qv.w;
        p += __shfl_xor_sync(~0u, p, 1);
        p += __shfl_xor_sync(~0u, p, 2);
        if ((lane & 3) == 0) s.lgk[k * 10 + h4] = p;
    }
    __syncwarp();

    // ---- Phase C2: logits via head-pair accumulators (4 ull regs) + softmax
    float lg[8];
    {
        ull acc01 = 0ull, acc23 = 0ull, acc45 = 0ull, acc67 = 0ull;
        const __half* drow = s.dist + lane * 36;
#pragma unroll
        for (int i = 0; i < 8; i++) {
            uint2 hv = *(const uint2*)(drow + i * 4);
            float2 f0 = __half22float2(*(__half2*)&hv.x);
            float2 f1 = __half22float2(*(__half2*)&hv.y);
            float dv[4] = {f0.x, f0.y, f1.x, f1.y};
#pragma unroll
            for (int e = 0; e < 4; e++) {
                int d = i * 4 + e;
                ull dv2 = pack2(dv[e], dv[e]);
                const ull* u = (const ull*)(s.ud_t + d * 8);
                acc01 = ffma2(u[0], dv2, acc01);
                acc23 = ffma2(u[1], dv2, acc23);
                acc45 = ffma2(u[2], dv2, acc45);
                acc67 = ffma2(u[3], dv2, acc67);
            }
        }
        const __half* srow = s.seq + lane * 20;
#pragma unroll
        for (int i = 0; i < 4; i++) {
            uint2 hv = *(const uint2*)(srow + i * 4);
            float2 f0 = __half22float2(*(__half2*)&hv.x);
            float2 f1 = __half22float2(*(__half2*)&hv.y);
            float sv[4] = {f0.x, f0.y, f1.x, f1.y};
#pragma unroll
            for (int e = 0; e < 4; e++) {
                int si = i * 4 + e;
                ull sv2 = pack2(sv[e], sv[e]);
                const ull* u = (const ull*)(s.us_t + si * 8);
                acc01 = ffma2(u[0], sv2, acc01);
                acc23 = ffma2(u[1], sv2, acc23);
                acc45 = ffma2(u[2], sv2, acc45);
                acc67 = ffma2(u[3], sv2, acc67);
            }
        }
        float2 p01 = unpack2(acc01), p23 = unpack2(acc23);
        float2 p45 = unpack2(acc45), p67 = unpack2(acc67);
        float pa[8] = {p01.x, p01.y, p23.x, p23.y, p45.x, p45.y, p67.x, p67.y};
#pragma unroll
        for (int h = 0; h < 8; h++)
            lg[h] = 0.25f * (s.lgk[lane * 10 + h] + pa[h] + s.c0[h]);
    }
#pragma unroll
    for (int h = 0; h < 8; h++) {
        float m = lg[h];
#pragma unroll
        for (int o = 16; o > 0; o >>= 1) m = fmaxf(m, __shfl_xor_sync(~0u, m, o));
        float e = __expf(lg[h] - m);
        float sm = e;
#pragma unroll
        for (int o = 16; o > 0; o >>= 1) sm += __shfl_xor_sync(~0u, sm, o);
        s.lgk[lane * 10 + h] = e / sm;
    }
    __syncwarp();

    // ---- Phase D: weighted sums — fp16 mv gather, 8B/lane
    const int sidx = lane & 15;
    float4 acc = make_float4(0.f, 0.f, 0.f, 0.f);
    ull sdl2[4] = {0ull, 0ull, 0ull, 0ull};
    float ssl[4] = {0.f, 0.f, 0.f, 0.f};
#pragma unroll 4
    for (int k = 0; k < 32; k++) {
        int j = s.jb[k];
        float a = s.lgk[k * 10 + h4];
        uint2 mr = *(const uint2*)(mvh + (long)j * 128 + lane * 4);
        float2 f0 = __half22float2(*(__half2*)&mr.x);
        float2 f1 = __half22float2(*(__half2*)&mr.y);
        acc.x += a * f0.x; acc.y += a * f0.y;
        acc.z += a * f1.x; acc.w += a * f1.y;
        float dv = __half2float(s.dist[k * 36 + lane]);
        ull dv2 = pack2(dv, dv);
        const ull* ap = (const ull*)(s.lgk + k * 10);
#pragma unroll
        for (int r = 0; r < 4; r++) sdl2[r] = ffma2(ap[r], dv2, sdl2[r]);
        float sv = __half2float(s.seq[k * 20 + sidx]);
#pragma unroll
        for (int r = 0; r < 4; r++) {
            int h2 = (lane >> 4) + 2 * r;
            ssl[r] += s.lgk[k * 10 + h2] * sv;
        }
    }
#pragma unroll
    for (int r = 0; r < 4; r++) {
        float2 p = unpack2(sdl2[r]);
        s.sd[(2 * r) * 32 + lane] = p.x;
        s.sd[(2 * r + 1) * 32 + lane] = p.y;
    }
#pragma unroll
    for (int r = 0; r < 4; r++) s.ss[lane + 32 * r] = ssl[r];
    __syncwarp();

    // ---- Phase D2: outv = acc + sd @ WvD + ss @ WvS + bv (f32x2)
    {
        const int i0 = lane * 4;
        float4 bvv = *(const float4*)(bv + i0);
        ull o01 = pack2(bvv.x + acc.x, bvv.y + acc.y);
        ull o23 = pack2(bvv.z + acc.z, bvv.w + acc.w);
#pragma unroll 8
        for (int d = 0; d < 32; d++) {
            float sdv = s.sd[h4 * 32 + d];
            ull s2 = pack2(sdv, sdv);
            ulonglong2 wv = *(const ulonglong2*)(Wv + (long)(128 + d) * 128 + i0);
            o01 = ffma2(wv.x, s2, o01);
            o23 = ffma2(wv.y, s2, o23);
        }
#pragma unroll 8
        for (int j = 0; j < 16; j++) {
            float ssv = s.ss[h4 * 16 + j];
            ull s2 = pack2(ssv, ssv);
            ulonglong2 wv = *(const ulonglong2*)(Wv + (long)(160 + j) * 128 + i0);
            o01 = ffma2(wv.x, s2, o01);
            o23 = ffma2(wv.y, s2, o23);
        }
        float2 p0 = unpack2(o01), p1 = unpack2(o23);
        *(float4*)(att_out + (long)n * 128 + i0) =
            make_float4(p0.x, p0.y, p1.x, p1.y);
    }
}

// ---------------- launch ----------------
extern "C" void kernel_launch(void* const* d_in, const int* in_sizes, int n_in,
                              void* d_out, int out_size)
{
    const float* features = (const float*)d_in[0];
    const float* distances = (const float*)d_in[1];
    const float* sequence = (const float*)d_in[2];
    const float* encoder = (const float*)d_in[3];
    const int*   idx = (const int*)d_in[4];
    const float* W1 = (const float*)d_in[5];
    const float* b1 = (const float*)d_in[6];
    const float* W2 = (const float*)d_in[7];
    const float* b2 = (const float*)d_in[8];
    const float* W3 = (const float*)d_in[9];
    const float* b3 = (const float*)d_in[10];
    const float* Wq = (const float*)d_in[11];
    const float* bq = (const float*)d_in[12];
    const float* Wk = (const float*)d_in[13];
    const float* bk = (const float*)d_in[14];
    const float* Wv = (const float*)d_in[15];
    const float* bv = (const float*)d_in[16];
    const float* Wo = (const float*)d_in[17];
    const float* bo = (const float*)d_in[18];

    float *h1, *h2, *msg, *q, *att;
    __half *mk, *mv;
    cudaGetSymbolAddress((void**)&h1, g_h1);
    cudaGetSymbolAddress((void**)&h2, g_h2);
    cudaGetSymbolAddress((void**)&msg, g_msg);
    cudaGetSymbolAddress((void**)&q, g_q);
    cudaGetSymbolAddress((void**)&mk, g_mk);
    cudaGetSymbolAddress((void**)&mv, g_mv);
    cudaGetSymbolAddress((void**)&att, g_att);

    const int gb = N_NODES / 64;  // 256 blocks
    gemm_h1_q<<<gb, 256>>>(features, W1, b1, Wq, bq, h1, q);           // 0
    gemm128<0, 1, 1, 0><<<gb, 256>>>(h1, W2, b2, nullptr, h2);         // 1
    gemm128<0, 1, 1, 1><<<gb, 256>>>(h2, W3, b3, encoder, msg);        // 2
    gemm128_dual_h<<<gb, 256>>>(msg, Wk, Wv, mk, mv);                  // 3
    attn_kernel<<<N_NODES / 4, 128>>>(distances, sequence, idx,        // 4
                                      q, mk, mv, Wk, bk, Wv, bv, att);
    gemm128<0, 0, 1, 1><<<gb, 256>>>(att, Wo, bo, features, (float*)d_out); // 5
}

// round 10
// speedup vs baseline: 1.0439x; 1.0439x over previous
#include <cuda_runtime.h>
#include <cuda_fp16.h>

#define N_NODES 16384
#define SZ 128
typedef unsigned long long ull;

__device__ __forceinline__ ull ffma2(ull a, ull b, ull c) {
    ull d;
    asm("fma.rn.f32x2 %0, %1, %2, %3;" : "=l"(d) : "l"(a), "l"(b), "l"(c));
    return d;
}
__device__ __forceinline__ ull pack2(float x, float y) {
    ull d;
    asm("mov.b64 %0, {%1, %2};" : "=l"(d) : "f"(x), "f"(y));
    return d;
}
__device__ __forceinline__ float2 unpack2(ull v) {
    float2 r;
    asm("mov.b64 {%0, %1}, %2;" : "=f"(r.x), "=f"(r.y) : "l"(v));
    return r;
}
__device__ __forceinline__ unsigned h2u(__half2 h) { return *(unsigned*)&h; }

// ---------------- scratch ----------------
__device__ float  g_h1[N_NODES * SZ];
__device__ float  g_h2[N_NODES * SZ];
__device__ float  g_msg[N_NODES * SZ];
__device__ float  g_q[N_NODES * SZ];
__device__ __half g_mk[N_NODES * SZ];
__device__ __half g_mv[N_NODES * SZ];
__device__ float  g_att[N_NODES * SZ];

// ---------------- GEMM (R4-proven): BM=64, BN=128, BK=32, 256 thr, 8x4/thr -
template <int RELU_IN, int RELU_OUT, int HAS_BIAS, int HAS_ADD>
__global__ __launch_bounds__(256) void gemm128(
    const float* __restrict__ A, const float* __restrict__ W,
    const float* __restrict__ bias, const float* __restrict__ add,
    float* __restrict__ C)
{
    __shared__ float As[32 * 64];    // [k][row]
    __shared__ float Ws[32 * 128];   // [k][col]
    const int t = threadIdx.x;
    const int tx = t & 31;
    const int ty = t >> 5;
    const int row0 = blockIdx.x * 64;

    float acc[8][4];
#pragma unroll
    for (int r = 0; r < 8; r++)
#pragma unroll
        for (int c = 0; c < 4; c++) acc[r][c] = 0.0f;

    for (int kt = 0; kt < 4; kt++) {
        const int kk0 = kt * 32;
        __syncthreads();
#pragma unroll
        for (int i = 0; i < 2; i++) {
            int f = t + i * 256;
            int r = f >> 3, c4 = f & 7;
            float4 v = *(const float4*)(A + (row0 + r) * 128 + kk0 + c4 * 4);
            if (RELU_IN) {
                v.x = fmaxf(v.x, 0.f); v.y = fmaxf(v.y, 0.f);
                v.z = fmaxf(v.z, 0.f); v.w = fmaxf(v.w, 0.f);
            }
            As[(c4 * 4 + 0) * 64 + r] = v.x;
            As[(c4 * 4 + 1) * 64 + r] = v.y;
            As[(c4 * 4 + 2) * 64 + r] = v.z;
            As[(c4 * 4 + 3) * 64 + r] = v.w;
        }
#pragma unroll
        for (int i = 0; i < 4; i++) {
            int f = t + i * 256;
            int kr = f >> 5, c4 = f & 31;
            *(float4*)(Ws + kr * 128 + c4 * 4) =
                *(const float4*)(W + (kk0 + kr) * 128 + c4 * 4);
        }
        __syncthreads();
#pragma unroll
        for (int kk = 0; kk < 32; kk++) {
            float4 a0 = *(const float4*)(As + kk * 64 + ty * 8);
            float4 a1 = *(const float4*)(As + kk * 64 + ty * 8 + 4);
            float4 w  = *(const float4*)(Ws + kk * 128 + tx * 4);
            float ar[8] = {a0.x, a0.y, a0.z, a0.w, a1.x, a1.y, a1.z, a1.w};
#pragma unroll
            for (int r = 0; r < 8; r++) {
                acc[r][0] += ar[r] * w.x;
                acc[r][1] += ar[r] * w.y;
                acc[r][2] += ar[r] * w.z;
                acc[r][3] += ar[r] * w.w;
            }
        }
    }

    float4 bz = make_float4(0.f, 0.f, 0.f, 0.f);
    if (HAS_BIAS) bz = *(const float4*)(bias + tx * 4);
#pragma unroll
    for (int r = 0; r < 8; r++) {
        int gr = row0 + ty * 8 + r;
        float4 o;
        o.x = acc[r][0] + bz.x;
        o.y = acc[r][1] + bz.y;
        o.z = acc[r][2] + bz.z;
        o.w = acc[r][3] + bz.w;
        if (RELU_OUT) {
            o.x = fmaxf(o.x, 0.f); o.y = fmaxf(o.y, 0.f);
            o.z = fmaxf(o.z, 0.f); o.w = fmaxf(o.w, 0.f);
        }
        if (HAS_ADD) {
            float4 av = *(const float4*)(add + gr * 128 + tx * 4);
            o.x += av.x; o.y += av.y; o.z += av.z; o.w += av.w;
        }
        *(float4*)(C + gr * 128 + tx * 4) = o;
    }
}

// ------- fused h1 & q: h1 = relu(relu(F)@W1+b1), q = F@Wq+bq (F loaded once)
__global__ __launch_bounds__(256) void gemm_h1_q(
    const float* __restrict__ F, const float* __restrict__ W1g,
    const float* __restrict__ b1, const float* __restrict__ Wqg,
    const float* __restrict__ bq, float* __restrict__ H1,
    float* __restrict__ Q)
{
    __shared__ float AsR[32 * 64];   // relu(F), [k][row]
    __shared__ float AsN[32 * 64];   // raw F
    __shared__ float Ws1[32 * 128];
    __shared__ float Ws2[32 * 128];
    const int t = threadIdx.x;
    const int tx = t & 31;
    const int ty = t >> 5;
    const int row0 = blockIdx.x * 64;

    float a1[8][4], a2[8][4];
#pragma unroll
    for (int r = 0; r < 8; r++)
#pragma unroll
        for (int c = 0; c < 4; c++) { a1[r][c] = 0.f; a2[r][c] = 0.f; }

    for (int kt = 0; kt < 4; kt++) {
        const int kk0 = kt * 32;
        __syncthreads();
#pragma unroll
        for (int i = 0; i < 2; i++) {
            int f = t + i * 256;
            int r = f >> 3, c4 = f & 7;
            float4 v = *(const float4*)(F + (row0 + r) * 128 + kk0 + c4 * 4);
            AsN[(c4 * 4 + 0) * 64 + r] = v.x;
            AsN[(c4 * 4 + 1) * 64 + r] = v.y;
            AsN[(c4 * 4 + 2) * 64 + r] = v.z;
            AsN[(c4 * 4 + 3) * 64 + r] = v.w;
            AsR[(c4 * 4 + 0) * 64 + r] = fmaxf(v.x, 0.f);
            AsR[(c4 * 4 + 1) * 64 + r] = fmaxf(v.y, 0.f);
            AsR[(c4 * 4 + 2) * 64 + r] = fmaxf(v.z, 0.f);
            AsR[(c4 * 4 + 3) * 64 + r] = fmaxf(v.w, 0.f);
        }
#pragma unroll
        for (int i = 0; i < 4; i++) {
            int f = t + i * 256;
            int kr = f >> 5, c4 = f & 31;
            *(float4*)(Ws1 + kr * 128 + c4 * 4) =
                *(const float4*)(W1g + (kk0 + kr) * 128 + c4 * 4);
            *(float4*)(Ws2 + kr * 128 + c4 * 4) =
                *(const float4*)(Wqg + (kk0 + kr) * 128 + c4 * 4);
        }
        __syncthreads();
#pragma unroll
        for (int kk = 0; kk < 32; kk++) {
            float4 r0 = *(const float4*)(AsR + kk * 64 + ty * 8);
            float4 r1 = *(const float4*)(AsR + kk * 64 + ty * 8 + 4);
            float4 n0 = *(const float4*)(AsN + kk * 64 + ty * 8);
            float4 n1 = *(const float4*)(AsN + kk * 64 + ty * 8 + 4);
            float4 w1 = *(const float4*)(Ws1 + kk * 128 + tx * 4);
            float4 w2 = *(const float4*)(Ws2 + kk * 128 + tx * 4);
            float rr[8] = {r0.x, r0.y, r0.z, r0.w, r1.x, r1.y, r1.z, r1.w};
            float nn[8] = {n0.x, n0.y, n0.z, n0.w, n1.x, n1.y, n1.z, n1.w};
#pragma unroll
            for (int r = 0; r < 8; r++) {
                a1[r][0] += rr[r] * w1.x; a1[r][1] += rr[r] * w1.y;
                a1[r][2] += rr[r] * w1.z; a1[r][3] += rr[r] * w1.w;
                a2[r][0] += nn[r] * w2.x; a2[r][1] += nn[r] * w2.y;
                a2[r][2] += nn[r] * w2.z; a2[r][3] += nn[r] * w2.w;
            }
        }
    }

    float4 bz1 = *(const float4*)(b1 + tx * 4);
    float4 bzq = *(const float4*)(bq + tx * 4);
#pragma unroll
    for (int r = 0; r < 8; r++) {
        int gr = row0 + ty * 8 + r;
        float4 o1 = make_float4(fmaxf(a1[r][0] + bz1.x, 0.f),
                                fmaxf(a1[r][1] + bz1.y, 0.f),
                                fmaxf(a1[r][2] + bz1.z, 0.f),
                                fmaxf(a1[r][3] + bz1.w, 0.f));
        float4 oq = make_float4(a2[r][0] + bzq.x, a2[r][1] + bzq.y,
                                a2[r][2] + bzq.z, a2[r][3] + bzq.w);
        *(float4*)(H1 + gr * 128 + tx * 4) = o1;
        *(float4*)(Q + gr * 128 + tx * 4) = oq;
    }
}

// ---------------- dual GEMM -> fp16: mk = A@Wk[:128], mv = A@Wv[:128] ------
__global__ __launch_bounds__(256) void gemm128_dual_h(
    const float* __restrict__ A, const float* __restrict__ W1g,
    const float* __restrict__ W2g, __half* __restrict__ C1,
    __half* __restrict__ C2)
{
    __shared__ float As[32 * 64];
    __shared__ float Ws1[32 * 128];
    __shared__ float Ws2[32 * 128];
    const int t = threadIdx.x;
    const int tx = t & 31;
    const int ty = t >> 5;
    const int row0 = blockIdx.x * 64;

    float a1[8][4], a2[8][4];
#pragma unroll
    for (int r = 0; r < 8; r++)
#pragma unroll
        for (int c = 0; c < 4; c++) { a1[r][c] = 0.f; a2[r][c] = 0.f; }

    for (int kt = 0; kt < 4; kt++) {
        const int kk0 = kt * 32;
        __syncthreads();
#pragma unroll
        for (int i = 0; i < 2; i++) {
            int f = t + i * 256;
            int r = f >> 3, c4 = f & 7;
            float4 v = *(const float4*)(A + (row0 + r) * 128 + kk0 + c4 * 4);
            As[(c4 * 4 + 0) * 64 + r] = v.x;
            As[(c4 * 4 + 1) * 64 + r] = v.y;
            As[(c4 * 4 + 2) * 64 + r] = v.z;
            As[(c4 * 4 + 3) * 64 + r] = v.w;
        }
#pragma unroll
        for (int i = 0; i < 4; i++) {
            int f = t + i * 256;
            int kr = f >> 5, c4 = f & 31;
            *(float4*)(Ws1 + kr * 128 + c4 * 4) =
                *(const float4*)(W1g + (kk0 + kr) * 128 + c4 * 4);
            *(float4*)(Ws2 + kr * 128 + c4 * 4) =
                *(const float4*)(W2g + (kk0 + kr) * 128 + c4 * 4);
        }
        __syncthreads();
#pragma unroll
        for (int kk = 0; kk < 32; kk++) {
            float4 a0 = *(const float4*)(As + kk * 64 + ty * 8);
            float4 a1r = *(const float4*)(As + kk * 64 + ty * 8 + 4);
            float4 w1 = *(const float4*)(Ws1 + kk * 128 + tx * 4);
            float4 w2 = *(const float4*)(Ws2 + kk * 128 + tx * 4);
            float ar[8] = {a0.x, a0.y, a0.z, a0.w, a1r.x, a1r.y, a1r.z, a1r.w};
#pragma unroll
            for (int r = 0; r < 8; r++) {
                a1[r][0] += ar[r] * w1.x; a1[r][1] += ar[r] * w1.y;
                a1[r][2] += ar[r] * w1.z; a1[r][3] += ar[r] * w1.w;
                a2[r][0] += ar[r] * w2.x; a2[r][1] += ar[r] * w2.y;
                a2[r][2] += ar[r] * w2.z; a2[r][3] += ar[r] * w2.w;
            }
        }
    }
#pragma unroll
    for (int r = 0; r < 8; r++) {
        int gr = row0 + ty * 8 + r;
        uint2 o1, o2;
        o1.x = h2u(__float22half2_rn(make_float2(a1[r][0], a1[r][1])));
        o1.y = h2u(__float22half2_rn(make_float2(a1[r][2], a1[r][3])));
        o2.x = h2u(__float22half2_rn(make_float2(a2[r][0], a2[r][1])));
        o2.y = h2u(__float22half2_rn(make_float2(a2[r][2], a2[r][3])));
        *(uint2*)(C1 + (long)gr * 128 + tx * 4) = o1;
        *(uint2*)(C2 + (long)gr * 128 + tx * 4) = o2;
    }
}

// ---------------- attention: 2 warps per node — halved serial chains -------
struct __align__(16) NodeSmem {
    __half dist[32 * 36];  // [k][d] pad-36 halves
    __half seq[32 * 20];   // [k][s] pad-20 halves
    float ud_t[32 * 8];    // [d][h]
    float us_t[16 * 8];    // [s][h]
    float c0[8];
    float lgk[32 * 10];    // [k][h] pad-10
    float sd[2][256];      // per-half partials [h*32+d]
    float ss[2][128];      // per-half partials (lane+32r layout)
    float accp[2][128];    // per-half acc partials
    int   jb[32];
};

__global__ __launch_bounds__(128) void attn_kernel(
    const float* __restrict__ dist_g, const float* __restrict__ seq_g,
    const int* __restrict__ idx, const float* __restrict__ qg,
    const __half* __restrict__ mkh, const __half* __restrict__ mvh,
    const float* __restrict__ Wk, const float* __restrict__ bk,
    const float* __restrict__ Wv, const float* __restrict__ bv,
    float* __restrict__ att_out)
{
    __shared__ NodeSmem S[2];
    const int lane = threadIdx.x & 31;
    const int w = threadIdx.x >> 5;
    const int half = w & 1;          // which half of k / rows / dims
    NodeSmem& s = S[w >> 1];
    const int n = blockIdx.x * 2 + (w >> 1);

    const float4 qv = ((const float4*)(qg + (long)n * 128))[lane];

    // ---- Stage (split between warp pair)
    if (half == 0) {
        s.jb[lane] = idx[n * 32 + lane];
        const float4* dg = (const float4*)(dist_g + (long)n * 1024);
#pragma unroll
        for (int it = 0; it < 4; it++) {
            int i4 = it * 32 + lane;
            float4 v = dg[i4];
            uint2 h;
            h.x = h2u(__float22half2_rn(make_float2(v.x, v.y)));
            h.y = h2u(__float22half2_rn(make_float2(v.z, v.w)));
            *(uint2*)(s.dist + (i4 >> 3) * 36 + (i4 & 7) * 4) = h;
        }
    } else {
        const float4* dg = (const float4*)(dist_g + (long)n * 1024);
#pragma unroll
        for (int it = 4; it < 8; it++) {
            int i4 = it * 32 + lane;
            float4 v = dg[i4];
            uint2 h;
            h.x = h2u(__float22half2_rn(make_float2(v.x, v.y)));
            h.y = h2u(__float22half2_rn(make_float2(v.z, v.w)));
            *(uint2*)(s.dist + (i4 >> 3) * 36 + (i4 & 7) * 4) = h;
        }
        const float4* sg = (const float4*)(seq_g + (long)n * 512);
#pragma unroll
        for (int it = 0; it < 4; it++) {
            int i4 = it * 32 + lane;
            float4 v = sg[i4];
            uint2 h;
            h.x = h2u(__float22half2_rn(make_float2(v.x, v.y)));
            h.y = h2u(__float22half2_rn(make_float2(v.z, v.w)));
            *(uint2*)(s.seq + (i4 >> 2) * 20 + (i4 & 3) * 4) = h;
        }
    }

    // ---- Phase B: fold rows split 24/24 (+bias on half 0)
    const int h4 = lane >> 2;
#pragma unroll 8
    for (int rr = 0; rr < 24; rr++) {
        int r = half * 24 + rr;
        float4 wv = *(const float4*)(Wk + (long)(128 + r) * 128 + lane * 4);
        float p = wv.x * qv.x + wv.y * qv.y + wv.z * qv.z + wv.w * qv.w;
        p += __shfl_xor_sync(~0u, p, 1);
        p += __shfl_xor_sync(~0u, p, 2);
        if ((lane & 3) == 0) {
            if (r < 32) s.ud_t[r * 8 + h4] = p;
            else        s.us_t[(r - 32) * 8 + h4] = p;
        }
    }
    if (half == 0) {
        float4 wv = *(const float4*)(bk + lane * 4);
        float p = wv.x * qv.x + wv.y * qv.y + wv.z * qv.z + wv.w * qv.w;
        p += __shfl_xor_sync(~0u, p, 1);
        p += __shfl_xor_sync(~0u, p, 2);
        if ((lane & 3) == 0) s.c0[h4] = p;
    }
    __syncthreads();   // staging + folds complete

    // ---- Phase C1: q . mk[jb[k]] for k in this warp's half
#pragma unroll 8
    for (int kk = 0; kk < 16; kk++) {
        int k = half * 16 + kk;
        int j = s.jb[k];
        uint2 mr = *(const uint2*)(mkh + (long)j * 128 + lane * 4);
        float2 f0 = __half22float2(*(__half2*)&mr.x);
        float2 f1 = __half22float2(*(__half2*)&mr.y);
        float p = f0.x * qv.x + f0.y * qv.y + f1.x * qv.z + f1.y * qv.w;
        p += __shfl_xor_sync(~0u, p, 1);
        p += __shfl_xor_sync(~0u, p, 2);
        if ((lane & 3) == 0) s.lgk[k * 10 + h4] = p;
    }
    __syncthreads();   // all lgk mk-parts written

    // ---- Phase C2 + softmax: each warp owns 4 heads (hbase = half*4)
    {
        ull acc01 = 0ull, acc23 = 0ull;   // head pairs (hb,hb+1),(hb+2,hb+3)
        const __half* drow = s.dist + lane * 36;
#pragma unroll
        for (int i = 0; i < 8; i++) {
            uint2 hv = *(const uint2*)(drow + i * 4);
            float2 f0 = __half22float2(*(__half2*)&hv.x);
            float2 f1 = __half22float2(*(__half2*)&hv.y);
            float dv[4] = {f0.x, f0.y, f1.x, f1.y};
#pragma unroll
            for (int e = 0; e < 4; e++) {
                int d = i * 4 + e;
                ull dv2 = pack2(dv[e], dv[e]);
                const ull* u = (const ull*)(s.ud_t + d * 8 + half * 4);
                acc01 = ffma2(u[0], dv2, acc01);
                acc23 = ffma2(u[1], dv2, acc23);
            }
        }
        const __half* srow = s.seq + lane * 20;
#pragma unroll
        for (int i = 0; i < 4; i++) {
            uint2 hv = *(const uint2*)(srow + i * 4);
            float2 f0 = __half22float2(*(__half2*)&hv.x);
            float2 f1 = __half22float2(*(__half2*)&hv.y);
            float sv[4] = {f0.x, f0.y, f1.x, f1.y};
#pragma unroll
            for (int e = 0; e < 4; e++) {
                int si = i * 4 + e;
                ull sv2 = pack2(sv[e], sv[e]);
                const ull* u = (const ull*)(s.us_t + si * 8 + half * 4);
                acc01 = ffma2(u[0], sv2, acc01);
                acc23 = ffma2(u[1], sv2, acc23);
            }
        }
        float2 pA = unpack2(acc01), pB = unpack2(acc23);
        float pa[4] = {pA.x, pA.y, pB.x, pB.y};
#pragma unroll
        for (int hh = 0; hh < 4; hh++) {
            int h = half * 4 + hh;
            float lg = 0.25f * (s.lgk[lane * 10 + h] + pa[hh] + s.c0[h]);
            float m = lg;
#pragma unroll
            for (int o = 16; o > 0; o >>= 1)
                m = fmaxf(m, __shfl_xor_sync(~0u, m, o));
            float e = __expf(lg - m);
            float sm = e;
#pragma unroll
            for (int o = 16; o > 0; o >>= 1)
                sm += __shfl_xor_sync(~0u, sm, o);
            s.lgk[lane * 10 + h] = e / sm;
        }
    }
    __syncthreads();   // all attn weights final

    // ---- Phase D: weighted sums over this warp's k-half -> partials
    {
        const int sidx = lane & 15;
        float4 acc = make_float4(0.f, 0.f, 0.f, 0.f);
        ull sdl2[4] = {0ull, 0ull, 0ull, 0ull};
        float ssl[4] = {0.f, 0.f, 0.f, 0.f};
#pragma unroll 4
        for (int kk = 0; kk < 16; kk++) {
            int k = half * 16 + kk;
            int j = s.jb[k];
            float a = s.lgk[k * 10 + h4];
            uint2 mr = *(const uint2*)(mvh + (long)j * 128 + lane * 4);
            float2 f0 = __half22float2(*(__half2*)&mr.x);
            float2 f1 = __half22float2(*(__half2*)&mr.y);
            acc.x += a * f0.x; acc.y += a * f0.y;
            acc.z += a * f1.x; acc.w += a * f1.y;
            float dv = __half2float(s.dist[k * 36 + lane]);
            ull dv2 = pack2(dv, dv);
            const ull* ap = (const ull*)(s.lgk + k * 10);
#pragma unroll
            for (int r = 0; r < 4; r++) sdl2[r] = ffma2(ap[r], dv2, sdl2[r]);
            float sv = __half2float(s.seq[k * 20 + sidx]);
#pragma unroll
            for (int r = 0; r < 4; r++) {
                int h2 = (lane >> 4) + 2 * r;
                ssl[r] += s.lgk[k * 10 + h2] * sv;
            }
        }
        *(float4*)(s.accp[half] + lane * 4) = acc;
#pragma unroll
        for (int r = 0; r < 4; r++) {
            float2 p = unpack2(sdl2[r]);
            s.sd[half][(2 * r) * 32 + lane] = p.x;
            s.sd[half][(2 * r + 1) * 32 + lane] = p.y;
        }
#pragma unroll
        for (int r = 0; r < 4; r++) s.ss[half][lane + 32 * r] = ssl[r];
    }
    __syncthreads();   // partials ready

    // ---- Phase D2: combine + project; this warp owns dims [half*64, +64)
    {
        const int i0 = half * 64 + lane * 2;
        const int h = i0 >> 4;
        float2 a0 = *(const float2*)(s.accp[0] + i0);
        float2 a1 = *(const float2*)(s.accp[1] + i0);
        float2 bb = *(const float2*)(bv + i0);
        ull o = pack2(a0.x + a1.x + bb.x, a0.y + a1.y + bb.y);
#pragma unroll 8
        for (int d = 0; d < 32; d++) {
            float sdv = s.sd[0][h * 32 + d] + s.sd[1][h * 32 + d];
            ull wv = *(const ull*)(Wv + (long)(128 + d) * 128 + i0);
            o = ffma2(wv, pack2(sdv, sdv), o);
        }
#pragma unroll 8
        for (int j2 = 0; j2 < 16; j2++) {
            int si = (h & 1) * 16 + j2 + 32 * (h >> 1);   // ss layout index
            float ssv = s.ss[0][si] + s.ss[1][si];
            ull wv = *(const ull*)(Wv + (long)(160 + j2) * 128 + i0);
            o = ffma2(wv, pack2(ssv, ssv), o);
        }
        float2 po = unpack2(o);
        *(float2*)(att_out + (long)n * 128 + i0) = po;
    }
}

// ---------------- launch ----------------
extern "C" void kernel_launch(void* const* d_in, const int* in_sizes, int n_in,
                              void* d_out, int out_size)
{
    const float* features = (const float*)d_in[0];
    const float* distances = (const float*)d_in[1];
    const float* sequence = (const float*)d_in[2];
    const float* encoder = (const float*)d_in[3];
    const int*   idx = (const int*)d_in[4];
    const float* W1 = (const float*)d_in[5];
    const float* b1 = (const float*)d_in[6];
    const float* W2 = (const float*)d_in[7];
    const float* b2 = (const float*)d_in[8];
    const float* W3 = (const float*)d_in[9];
    const float* b3 = (const float*)d_in[10];
    const float* Wq = (const float*)d_in[11];
    const float* bq = (const float*)d_in[12];
    const float* Wk = (const float*)d_in[13];
    const float* bk = (const float*)d_in[14];
    const float* Wv = (const float*)d_in[15];
    const float* bv = (const float*)d_in[16];
    const float* Wo = (const float*)d_in[17];
    const float* bo = (const float*)d_in[18];

    float *h1, *h2, *msg, *q, *att;
    __half *mk, *mv;
    cudaGetSymbolAddress((void**)&h1, g_h1);
    cudaGetSymbolAddress((void**)&h2, g_h2);
    cudaGetSymbolAddress((void**)&msg, g_msg);
    cudaGetSymbolAddress((void**)&q, g_q);
    cudaGetSymbolAddress((void**)&mk, g_mk);
    cudaGetSymbolAddress((void**)&mv, g_mv);
    cudaGetSymbolAddress((void**)&att, g_att);

    const int gb = N_NODES / 64;  // 256 blocks
    gemm_h1_q<<<gb, 256>>>(features, W1, b1, Wq, bq, h1, q);           // 0
    gemm128<0, 1, 1, 0><<<gb, 256>>>(h1, W2, b2, nullptr, h2);         // 1
    gemm128<0, 1, 1, 1><<<gb, 256>>>(h2, W3, b3, encoder, msg);        // 2
    gemm128_dual_h<<<gb, 256>>>(msg, Wk, Wv, mk, mv);                  // 3
    attn_kernel<<<N_NODES / 2, 128>>>(distances, sequence, idx,        // 4
                                      q, mk, mv, Wk, bk, Wv, bv, att);
    gemm128<0, 0, 1, 1><<<gb, 256>>>(att, Wo, bo, features, (float*)d_out); // 5
}

// round 11
// speedup vs baseline: 1.2655x; 1.2122x over previous
#include <cuda_runtime.h>
#include <cuda_fp16.h>

#define N_NODES 16384
#define SZ 128
#define APAD 132   // smem row pad (floats): stride 528B -> conflict-free frags
typedef unsigned long long ull;
typedef unsigned int uint32;

__device__ __forceinline__ ull ffma2(ull a, ull b, ull c) {
    ull d;
    asm("fma.rn.f32x2 %0, %1, %2, %3;" : "=l"(d) : "l"(a), "l"(b), "l"(c));
    return d;
}
__device__ __forceinline__ ull pack2(float x, float y) {
    ull d;
    asm("mov.b64 %0, {%1, %2};" : "=l"(d) : "f"(x), "f"(y));
    return d;
}
__device__ __forceinline__ float2 unpack2(ull v) {
    float2 r;
    asm("mov.b64 {%0, %1}, %2;" : "=f"(r.x), "=f"(r.y) : "l"(v));
    return r;
}
__device__ __forceinline__ unsigned h2u(__half2 h) { return *(unsigned*)&h; }
__device__ __forceinline__ float to_tf32(float x) {
    uint32 u;
    asm("cvt.rna.tf32.f32 %0, %1;" : "=r"(u) : "f"(x));
    return __uint_as_float(u);
}
__device__ __forceinline__ void mma_tf32(float* c, uint32 a0, uint32 a1,
                                         uint32 a2, uint32 a3,
                                         uint32 b0, uint32 b1) {
    asm volatile(
        "mma.sync.aligned.m16n8k8.row.col.f32.tf32.tf32.f32 "
        "{%0,%1,%2,%3}, {%4,%5,%6,%7}, {%8,%9}, {%0,%1,%2,%3};"
        : "+f"(c[0]), "+f"(c[1]), "+f"(c[2]), "+f"(c[3])
        : "r"(a0), "r"(a1), "r"(a2), "r"(a3), "r"(b0), "r"(b1));
}

// ---------------- scratch ----------------
__device__ float  g_h1[N_NODES * SZ];
__device__ float  g_h2[N_NODES * SZ];
__device__ float  g_msg[N_NODES * SZ];
__device__ float  g_q[N_NODES * SZ];
__device__ __half g_mk[N_NODES * SZ];
__device__ __half g_mv[N_NODES * SZ];
__device__ float  g_att[N_NODES * SZ];

// ---------------- tensor-core GEMM: C[N,128] = f(A[N,128]@W[128,128]+b)(+add)
// tf32 mma m16n8k8. Block: 64 rows x 128 cols, 256 thr (8 warps, each 16x64).
// Full K=128 resident in smem; pad-132 rows -> conflict-free fragment loads.
template <int RELU_IN, int RELU_OUT, int HAS_BIAS, int HAS_ADD, int OUT_HALF>
__global__ __launch_bounds__(256) void tgemm(
    const float* __restrict__ A, const float* __restrict__ W,
    const float* __restrict__ bias, const float* __restrict__ add,
    void* __restrict__ Cv)
{
    extern __shared__ float sm[];
    float* As = sm;                 // [64][APAD]
    float* Ws = sm + 64 * APAD;     // [128][APAD]
    const int t = threadIdx.x;
    const int lane = t & 31, w = t >> 5;
    const int mw = w & 3, nw = w >> 2;
    const int g = lane >> 2, tig = lane & 3;
    const long row0 = (long)blockIdx.x * 64;

    // ---- stage A tile (fp32 -> tf32)
#pragma unroll
    for (int i = 0; i < 8; i++) {
        int idx = t + i * 256;
        int r = idx >> 5, c4 = idx & 31;
        float4 v = *(const float4*)(A + (row0 + r) * 128 + c4 * 4);
        if (RELU_IN) {
            v.x = fmaxf(v.x, 0.f); v.y = fmaxf(v.y, 0.f);
            v.z = fmaxf(v.z, 0.f); v.w = fmaxf(v.w, 0.f);
        }
        float4 o = make_float4(to_tf32(v.x), to_tf32(v.y),
                               to_tf32(v.z), to_tf32(v.w));
        *(float4*)(As + r * APAD + c4 * 4) = o;
    }
    // ---- stage W tile (fp32 -> tf32)
#pragma unroll
    for (int i = 0; i < 16; i++) {
        int idx = t + i * 256;
        int r = idx >> 5, c4 = idx & 31;
        float4 v = *(const float4*)(W + r * 128 + c4 * 4);
        float4 o = make_float4(to_tf32(v.x), to_tf32(v.y),
                               to_tf32(v.z), to_tf32(v.w));
        *(float4*)(Ws + r * APAD + c4 * 4) = o;
    }
    __syncthreads();

    float acc[8][4];
#pragma unroll
    for (int nt = 0; nt < 8; nt++)
#pragma unroll
        for (int c = 0; c < 4; c++) acc[nt][c] = 0.f;

    const int ar = mw * 16;
    const int nc0 = nw * 64;
#pragma unroll
    for (int ks = 0; ks < 16; ks++) {
        const int k0 = ks * 8;
        uint32 a0 = __float_as_uint(As[(ar + g) * APAD + k0 + tig]);
        uint32 a1 = __float_as_uint(As[(ar + g + 8) * APAD + k0 + tig]);
        uint32 a2 = __float_as_uint(As[(ar + g) * APAD + k0 + tig + 4]);
        uint32 a3 = __float_as_uint(As[(ar + g + 8) * APAD + k0 + tig + 4]);
#pragma unroll
        for (int nt = 0; nt < 8; nt++) {
            int nc = nc0 + nt * 8 + g;
            uint32 b0 = __float_as_uint(Ws[(k0 + tig) * APAD + nc]);
            uint32 b1 = __float_as_uint(Ws[(k0 + tig + 4) * APAD + nc]);
            mma_tf32(acc[nt], a0, a1, a2, a3, b0, b1);
        }
    }

    // ---- epilogue: c0,c1 -> (row g, cols 2tig..); c2,c3 -> row g+8
#pragma unroll
    for (int nt = 0; nt < 8; nt++) {
        int col = nc0 + nt * 8 + tig * 2;
        long r0 = row0 + ar + g;
        long r1 = r0 + 8;
        float2 bz = make_float2(0.f, 0.f);
        if (HAS_BIAS) bz = *(const float2*)(bias + col);
        float2 v0 = make_float2(acc[nt][0] + bz.x, acc[nt][1] + bz.y);
        float2 v1 = make_float2(acc[nt][2] + bz.x, acc[nt][3] + bz.y);
        if (RELU_OUT) {
            v0.x = fmaxf(v0.x, 0.f); v0.y = fmaxf(v0.y, 0.f);
            v1.x = fmaxf(v1.x, 0.f); v1.y = fmaxf(v1.y, 0.f);
        }
        if (HAS_ADD) {
            float2 q0 = *(const float2*)(add + r0 * 128 + col);
            float2 q1 = *(const float2*)(add + r1 * 128 + col);
            v0.x += q0.x; v0.y += q0.y;
            v1.x += q1.x; v1.y += q1.y;
        }
        if (OUT_HALF) {
            __half* C = (__half*)Cv;
            *(__half2*)(C + r0 * 128 + col) = __float22half2_rn(v0);
            *(__half2*)(C + r1 * 128 + col) = __float22half2_rn(v1);
        } else {
            float* C = (float*)Cv;
            *(float2*)(C + r0 * 128 + col) = v0;
            *(float2*)(C + r1 * 128 + col) = v1;
        }
    }
}

// ---------------- attention: 2 warps per node (unchanged, R10-proven) ------
struct __align__(16) NodeSmem {
    __half dist[32 * 36];
    __half seq[32 * 20];
    float ud_t[32 * 8];
    float us_t[16 * 8];
    float c0[8];
    float lgk[32 * 10];
    float sd[2][256];
    float ss[2][128];
    float accp[2][128];
    int   jb[32];
};

__global__ __launch_bounds__(128) void attn_kernel(
    const float* __restrict__ dist_g, const float* __restrict__ seq_g,
    const int* __restrict__ idx, const float* __restrict__ qg,
    const __half* __restrict__ mkh, const __half* __restrict__ mvh,
    const float* __restrict__ Wk, const float* __restrict__ bk,
    const float* __restrict__ Wv, const float* __restrict__ bv,
    float* __restrict__ att_out)
{
    __shared__ NodeSmem S[2];
    const int lane = threadIdx.x & 31;
    const int w = threadIdx.x >> 5;
    const int half = w & 1;
    NodeSmem& s = S[w >> 1];
    const int n = blockIdx.x * 2 + (w >> 1);

    const float4 qv = ((const float4*)(qg + (long)n * 128))[lane];

    if (half == 0) {
        s.jb[lane] = idx[n * 32 + lane];
        const float4* dg = (const float4*)(dist_g + (long)n * 1024);
#pragma unroll
        for (int it = 0; it < 4; it++) {
            int i4 = it * 32 + lane;
            float4 v = dg[i4];
            uint2 h;
            h.x = h2u(__float22half2_rn(make_float2(v.x, v.y)));
            h.y = h2u(__float22half2_rn(make_float2(v.z, v.w)));
            *(uint2*)(s.dist + (i4 >> 3) * 36 + (i4 & 7) * 4) = h;
        }
    } else {
        const float4* dg = (const float4*)(dist_g + (long)n * 1024);
#pragma unroll
        for (int it = 4; it < 8; it++) {
            int i4 = it * 32 + lane;
            float4 v = dg[i4];
            uint2 h;
            h.x = h2u(__float22half2_rn(make_float2(v.x, v.y)));
            h.y = h2u(__float22half2_rn(make_float2(v.z, v.w)));
            *(uint2*)(s.dist + (i4 >> 3) * 36 + (i4 & 7) * 4) = h;
        }
        const float4* sg = (const float4*)(seq_g + (long)n * 512);
#pragma unroll
        for (int it = 0; it < 4; it++) {
            int i4 = it * 32 + lane;
            float4 v = sg[i4];
            uint2 h;
            h.x = h2u(__float22half2_rn(make_float2(v.x, v.y)));
            h.y = h2u(__float22half2_rn(make_float2(v.z, v.w)));
            *(uint2*)(s.seq + (i4 >> 2) * 20 + (i4 & 3) * 4) = h;
        }
    }

    const int h4 = lane >> 2;
#pragma unroll 8
    for (int rr = 0; rr < 24; rr++) {
        int r = half * 24 + rr;
        float4 wv = *(const float4*)(Wk + (long)(128 + r) * 128 + lane * 4);
        float p = wv.x * qv.x + wv.y * qv.y + wv.z * qv.z + wv.w * qv.w;
        p += __shfl_xor_sync(~0u, p, 1);
        p += __shfl_xor_sync(~0u, p, 2);
        if ((lane & 3) == 0) {
            if (r < 32) s.ud_t[r * 8 + h4] = p;
            else        s.us_t[(r - 32) * 8 + h4] = p;
        }
    }
    if (half == 0) {
        float4 wv = *(const float4*)(bk + lane * 4);
        float p = wv.x * qv.x + wv.y * qv.y + wv.z * qv.z + wv.w * qv.w;
        p += __shfl_xor_sync(~0u, p, 1);
        p += __shfl_xor_sync(~0u, p, 2);
        if ((lane & 3) == 0) s.c0[h4] = p;
    }
    __syncthreads();

#pragma unroll 8
    for (int kk = 0; kk < 16; kk++) {
        int k = half * 16 + kk;
        int j = s.jb[k];
        uint2 mr = *(const uint2*)(mkh + (long)j * 128 + lane * 4);
        float2 f0 = __half22float2(*(__half2*)&mr.x);
        float2 f1 = __half22float2(*(__half2*)&mr.y);
        float p = f0.x * qv.x + f0.y * qv.y + f1.x * qv.z + f1.y * qv.w;
        p += __shfl_xor_sync(~0u, p, 1);
        p += __shfl_xor_sync(~0u, p, 2);
        if ((lane & 3) == 0) s.lgk[k * 10 + h4] = p;
    }
    __syncthreads();

    {
        ull acc01 = 0ull, acc23 = 0ull;
        const __half* drow = s.dist + lane * 36;
#pragma unroll
        for (int i = 0; i < 8; i++) {
            uint2 hv = *(const uint2*)(drow + i * 4);
            float2 f0 = __half22float2(*(__half2*)&hv.x);
            float2 f1 = __half22float2(*(__half2*)&hv.y);
            float dv[4] = {f0.x, f0.y, f1.x, f1.y};
#pragma unroll
            for (int e = 0; e < 4; e++) {
                int d = i * 4 + e;
                ull dv2 = pack2(dv[e], dv[e]);
                const ull* u = (const ull*)(s.ud_t + d * 8 + half * 4);
                acc01 = ffma2(u[0], dv2, acc01);
                acc23 = ffma2(u[1], dv2, acc23);
            }
        }
        const __half* srow = s.seq + lane * 20;
#pragma unroll
        for (int i = 0; i < 4; i++) {
            uint2 hv = *(const uint2*)(srow + i * 4);
            float2 f0 = __half22float2(*(__half2*)&hv.x);
            float2 f1 = __half22float2(*(__half2*)&hv.y);
            float sv[4] = {f0.x, f0.y, f1.x, f1.y};
#pragma unroll
            for (int e = 0; e < 4; e++) {
                int si = i * 4 + e;
                ull sv2 = pack2(sv[e], sv[e]);
                const ull* u = (const ull*)(s.us_t + si * 8 + half * 4);
                acc01 = ffma2(u[0], sv2, acc01);
                acc23 = ffma2(u[1], sv2, acc23);
            }
        }
        float2 pA = unpack2(acc01), pB = unpack2(acc23);
        float pa[4] = {pA.x, pA.y, pB.x, pB.y};
#pragma unroll
        for (int hh = 0; hh < 4; hh++) {
            int h = half * 4 + hh;
            float lg = 0.25f * (s.lgk[lane * 10 + h] + pa[hh] + s.c0[h]);
            float m = lg;
#pragma unroll
            for (int o = 16; o > 0; o >>= 1)
                m = fmaxf(m, __shfl_xor_sync(~0u, m, o));
            float e = __expf(lg - m);
            float sm = e;
#pragma unroll
            for (int o = 16; o > 0; o >>= 1)
                sm += __shfl_xor_sync(~0u, sm, o);
            s.lgk[lane * 10 + h] = e / sm;
        }
    }
    __syncthreads();

    {
        const int sidx = lane & 15;
        float4 acc = make_float4(0.f, 0.f, 0.f, 0.f);
        ull sdl2[4] = {0ull, 0ull, 0ull, 0ull};
        float ssl[4] = {0.f, 0.f, 0.f, 0.f};
#pragma unroll 4
        for (int kk = 0; kk < 16; kk++) {
            int k = half * 16 + kk;
            int j = s.jb[k];
            float a = s.lgk[k * 10 + h4];
            uint2 mr = *(const uint2*)(mvh + (long)j * 128 + lane * 4);
            float2 f0 = __half22float2(*(__half2*)&mr.x);
            float2 f1 = __half22float2(*(__half2*)&mr.y);
            acc.x += a * f0.x; acc.y += a * f0.y;
            acc.z += a * f1.x; acc.w += a * f1.y;
            float dv = __half2float(s.dist[k * 36 + lane]);
            ull dv2 = pack2(dv, dv);
            const ull* ap = (const ull*)(s.lgk + k * 10);
#pragma unroll
            for (int r = 0; r < 4; r++) sdl2[r] = ffma2(ap[r], dv2, sdl2[r]);
            float sv = __half2float(s.seq[k * 20 + sidx]);
#pragma unroll
            for (int r = 0; r < 4; r++) {
                int h2 = (lane >> 4) + 2 * r;
                ssl[r] += s.lgk[k * 10 + h2] * sv;
            }
        }
        *(float4*)(s.accp[half] + lane * 4) = acc;
#pragma unroll
        for (int r = 0; r < 4; r++) {
            float2 p = unpack2(sdl2[r]);
            s.sd[half][(2 * r) * 32 + lane] = p.x;
            s.sd[half][(2 * r + 1) * 32 + lane] = p.y;
        }
#pragma unroll
        for (int r = 0; r < 4; r++) s.ss[half][lane + 32 * r] = ssl[r];
    }
    __syncthreads();

    {
        const int i0 = half * 64 + lane * 2;
        const int h = i0 >> 4;
        float2 a0 = *(const float2*)(s.accp[0] + i0);
        float2 a1 = *(const float2*)(s.accp[1] + i0);
        float2 bb = *(const float2*)(bv + i0);
        ull o = pack2(a0.x + a1.x + bb.x, a0.y + a1.y + bb.y);
#pragma unroll 8
        for (int d = 0; d < 32; d++) {
            float sdv = s.sd[0][h * 32 + d] + s.sd[1][h * 32 + d];
            ull wv = *(const ull*)(Wv + (long)(128 + d) * 128 + i0);
            o = ffma2(wv, pack2(sdv, sdv), o);
        }
#pragma unroll 8
        for (int j2 = 0; j2 < 16; j2++) {
            int si = (h & 1) * 16 + j2 + 32 * (h >> 1);
            float ssv = s.ss[0][si] + s.ss[1][si];
            ull wv = *(const ull*)(Wv + (long)(160 + j2) * 128 + i0);
            o = ffma2(wv, pack2(ssv, ssv), o);
        }
        float2 po = unpack2(o);
        *(float2*)(att_out + (long)n * 128 + i0) = po;
    }
}

// ---------------- launch ----------------
#define TG_SMEM ((64 + 128) * APAD * 4)

extern "C" void kernel_launch(void* const* d_in, const int* in_sizes, int n_in,
                              void* d_out, int out_size)
{
    const float* features = (const float*)d_in[0];
    const float* distances = (const float*)d_in[1];
    const float* sequence = (const float*)d_in[2];
    const float* encoder = (const float*)d_in[3];
    const int*   idx = (const int*)d_in[4];
    const float* W1 = (const float*)d_in[5];
    const float* b1 = (const float*)d_in[6];
    const float* W2 = (const float*)d_in[7];
    const float* b2 = (const float*)d_in[8];
    const float* W3 = (const float*)d_in[9];
    const float* b3 = (const float*)d_in[10];
    const float* Wq = (const float*)d_in[11];
    const float* bq = (const float*)d_in[12];
    const float* Wk = (const float*)d_in[13];
    const float* bk = (const float*)d_in[14];
    const float* Wv = (const float*)d_in[15];
    const float* bv = (const float*)d_in[16];
    const float* Wo = (const float*)d_in[17];
    const float* bo = (const float*)d_in[18];

    float *h1, *h2, *msg, *q, *att;
    __half *mk, *mv;
    cudaGetSymbolAddress((void**)&h1, g_h1);
    cudaGetSymbolAddress((void**)&h2, g_h2);
    cudaGetSymbolAddress((void**)&msg, g_msg);
    cudaGetSymbolAddress((void**)&q, g_q);
    cudaGetSymbolAddress((void**)&mk, g_mk);
    cudaGetSymbolAddress((void**)&mv, g_mv);
    cudaGetSymbolAddress((void**)&att, g_att);

    // opt-in dynamic smem (idempotent; host-side attribute, capture-safe)
    cudaFuncSetAttribute(tgemm<1,1,1,0,0>, cudaFuncAttributeMaxDynamicSharedMemorySize, TG_SMEM);
    cudaFuncSetAttribute(tgemm<0,0,1,0,0>, cudaFuncAttributeMaxDynamicSharedMemorySize, TG_SMEM);
    cudaFuncSetAttribute(tgemm<0,1,1,0,0>, cudaFuncAttributeMaxDynamicSharedMemorySize, TG_SMEM);
    cudaFuncSetAttribute(tgemm<0,1,1,1,0>, cudaFuncAttributeMaxDynamicSharedMemorySize, TG_SMEM);
    cudaFuncSetAttribute(tgemm<0,0,0,0,1>, cudaFuncAttributeMaxDynamicSharedMemorySize, TG_SMEM);
    cudaFuncSetAttribute(tgemm<0,0,1,1,0>, cudaFuncAttributeMaxDynamicSharedMemorySize, TG_SMEM);

    const int gb = N_NODES / 64;  // 256 blocks
    // h1 = relu(relu(F)@W1 + b1)
    tgemm<1,1,1,0,0><<<gb, 256, TG_SMEM>>>(features, W1, b1, nullptr, h1);
    // q = F@Wq + bq
    tgemm<0,0,1,0,0><<<gb, 256, TG_SMEM>>>(features, Wq, bq, nullptr, q);
    // h2 = relu(h1@W2 + b2)
    tgemm<0,1,1,0,0><<<gb, 256, TG_SMEM>>>(h1, W2, b2, nullptr, h2);
    // msg = relu(h2@W3 + b3) + encoder
    tgemm<0,1,1,1,0><<<gb, 256, TG_SMEM>>>(h2, W3, b3, encoder, msg);
    // mk = msg@Wk[:128]  (fp16 out), mv = msg@Wv[:128]
    tgemm<0,0,0,0,1><<<gb, 256, TG_SMEM>>>(msg, Wk, nullptr, nullptr, mk);
    tgemm<0,0,0,0,1><<<gb, 256, TG_SMEM>>>(msg, Wv, nullptr, nullptr, mv);
    // attention (unchanged)
    attn_kernel<<<N_NODES / 2, 128>>>(distances, sequence, idx,
                                      q, mk, mv, Wk, bk, Wv, bv, att);
    // out = features + att@Wo + bo
    tgemm<0,0,1,1,0><<<gb, 256, TG_SMEM>>>(att, Wo, bo, features, (float*)d_out);
}

// round 12
// speedup vs baseline: 1.3927x; 1.1006x over previous
#include <cuda_runtime.h>
#include <cuda_fp16.h>

#define N_NODES 16384
#define SZ 128
#define KPAD 136   // halfs per smem row: 272B -> ldmatrix rows on banks 4r..4r+3
typedef unsigned long long ull;
typedef unsigned int uint32;

__device__ __forceinline__ ull ffma2(ull a, ull b, ull c) {
    ull d;
    asm("fma.rn.f32x2 %0, %1, %2, %3;" : "=l"(d) : "l"(a), "l"(b), "l"(c));
    return d;
}
__device__ __forceinline__ ull pack2(float x, float y) {
    ull d;
    asm("mov.b64 %0, {%1, %2};" : "=l"(d) : "f"(x), "f"(y));
    return d;
}
__device__ __forceinline__ float2 unpack2(ull v) {
    float2 r;
    asm("mov.b64 {%0, %1}, %2;" : "=f"(r.x), "=f"(r.y) : "l"(v));
    return r;
}
__device__ __forceinline__ unsigned h2u(__half2 h) { return *(unsigned*)&h; }

__device__ __forceinline__ void ldsm_x4(uint32& r0, uint32& r1, uint32& r2,
                                        uint32& r3, uint32 addr) {
    asm volatile("ldmatrix.sync.aligned.m8n8.x4.shared.b16 {%0,%1,%2,%3}, [%4];"
                 : "=r"(r0), "=r"(r1), "=r"(r2), "=r"(r3) : "r"(addr));
}
__device__ __forceinline__ void ldsm_x2t(uint32& r0, uint32& r1, uint32 addr) {
    asm volatile("ldmatrix.sync.aligned.m8n8.x2.trans.shared.b16 {%0,%1}, [%2];"
                 : "=r"(r0), "=r"(r1) : "r"(addr));
}
__device__ __forceinline__ void mma_f16(float* c, uint32 a0, uint32 a1,
                                        uint32 a2, uint32 a3,
                                        uint32 b0, uint32 b1) {
    asm volatile(
        "mma.sync.aligned.m16n8k16.row.col.f32.f16.f16.f32 "
        "{%0,%1,%2,%3}, {%4,%5,%6,%7}, {%8,%9}, {%0,%1,%2,%3};"
        : "+f"(c[0]), "+f"(c[1]), "+f"(c[2]), "+f"(c[3])
        : "r"(a0), "r"(a1), "r"(a2), "r"(a3), "r"(b0), "r"(b1));
}

// ---------------- scratch ----------------
__device__ float  g_h1[N_NODES * SZ];
__device__ float  g_h2[N_NODES * SZ];
__device__ float  g_msg[N_NODES * SZ];
__device__ float  g_q[N_NODES * SZ];
__device__ __half g_mk[N_NODES * SZ];
__device__ __half g_mv[N_NODES * SZ];
__device__ float  g_att[N_NODES * SZ];

// ------- fp16 tensor-core GEMM: C[N,128] = f(A[N,128]@W[128,128]+b)(+add)
// mma m16n8k16 + ldmatrix. Block: 32 rows x 128 cols, 256 thr (2x4 warps,
// each 16x32). Full K in smem as fp16; KPAD=136 -> conflict-free ldmatrix.
template <int RELU_IN, int RELU_OUT, int HAS_BIAS, int HAS_ADD, int OUT_HALF>
__global__ __launch_bounds__(256) void tgemm(
    const float* __restrict__ A, const float* __restrict__ W,
    const float* __restrict__ bias, const float* __restrict__ add,
    void* __restrict__ Cv)
{
    extern __shared__ __half sm[];
    __half* As = sm;                 // [32][KPAD]
    __half* Ws = sm + 32 * KPAD;     // [128][KPAD]
    const int t = threadIdx.x;
    const int lane = t & 31, w = t >> 5;
    const int mw = w & 1, nw = w >> 1;       // 2 row-warps x 4 col-warps
    const long row0 = (long)blockIdx.x * 32;

    // ---- stage A tile (fp32 -> fp16), 32x128
#pragma unroll
    for (int i = 0; i < 4; i++) {
        int idx = t + i * 256;
        int r = idx >> 5, c4 = idx & 31;
        float4 v = *(const float4*)(A + (row0 + r) * 128 + c4 * 4);
        if (RELU_IN) {
            v.x = fmaxf(v.x, 0.f); v.y = fmaxf(v.y, 0.f);
            v.z = fmaxf(v.z, 0.f); v.w = fmaxf(v.w, 0.f);
        }
        uint2 pkt = make_uint2(h2u(__float22half2_rn(make_float2(v.x, v.y))),
                               h2u(__float22half2_rn(make_float2(v.z, v.w))));
        *(uint2*)(As + r * KPAD + c4 * 4) = pkt;
    }
    // ---- stage W tile (fp32 -> fp16), 128x128 row-major [k][n]
#pragma unroll
    for (int i = 0; i < 16; i++) {
        int idx = t + i * 256;
        int r = idx >> 5, c4 = idx & 31;
        float4 v = *(const float4*)(W + r * 128 + c4 * 4);
        uint2 pkt = make_uint2(h2u(__float22half2_rn(make_float2(v.x, v.y))),
                               h2u(__float22half2_rn(make_float2(v.z, v.w))));
        *(uint2*)(Ws + r * KPAD + c4 * 4) = pkt;
    }
    __syncthreads();

    float acc[4][4];
#pragma unroll
    for (int nt = 0; nt < 4; nt++)
#pragma unroll
        for (int c = 0; c < 4; c++) acc[nt][c] = 0.f;

    const int ar = mw * 16;          // warp row base within tile
    const int nc0 = nw * 32;         // warp col base
    const uint32 a_base = (uint32)__cvta_generic_to_shared(As);
    const uint32 w_base = (uint32)__cvta_generic_to_shared(Ws);

    // ldmatrix lane address offsets
    const int lrow = lane & 7, quad = lane >> 3;
    const uint32 a_off =
        ((uint32)(ar + lrow + ((quad & 1) << 3)) * KPAD + ((quad & 2) << 2)) * 2;
    const uint32 b_krow = (lane & 7) + (lane & 8);   // lanes 0-15 used by x2

#pragma unroll
    for (int ks = 0; ks < 8; ks++) {
        const int k0 = ks * 16;
        uint32 a0, a1, a2, a3;
        ldsm_x4(a0, a1, a2, a3, a_base + a_off + k0 * 2);
        uint32 baddr = w_base + ((k0 + b_krow) * KPAD + nc0) * 2;
#pragma unroll
        for (int nt = 0; nt < 4; nt++) {
            uint32 b0, b1;
            ldsm_x2t(b0, b1, baddr + nt * 16);   // +8 cols = 16B
            mma_f16(acc[nt], a0, a1, a2, a3, b0, b1);
        }
    }

    // ---- epilogue: c0,c1 -> (row g, col 2tig..); c2,c3 -> row g+8
    const int g = lane >> 2, tig = lane & 3;
#pragma unroll
    for (int nt = 0; nt < 4; nt++) {
        int col = nc0 + nt * 8 + tig * 2;
        long r0 = row0 + ar + g;
        long r1 = r0 + 8;
        float2 bz = make_float2(0.f, 0.f);
        if (HAS_BIAS) bz = *(const float2*)(bias + col);
        float2 v0 = make_float2(acc[nt][0] + bz.x, acc[nt][1] + bz.y);
        float2 v1 = make_float2(acc[nt][2] + bz.x, acc[nt][3] + bz.y);
        if (RELU_OUT) {
            v0.x = fmaxf(v0.x, 0.f); v0.y = fmaxf(v0.y, 0.f);
            v1.x = fmaxf(v1.x, 0.f); v1.y = fmaxf(v1.y, 0.f);
        }
        if (HAS_ADD) {
            float2 q0 = *(const float2*)(add + r0 * 128 + col);
            float2 q1 = *(const float2*)(add + r1 * 128 + col);
            v0.x += q0.x; v0.y += q0.y;
            v1.x += q1.x; v1.y += q1.y;
        }
        if (OUT_HALF) {
            __half* C = (__half*)Cv;
            *(__half2*)(C + r0 * 128 + col) = __float22half2_rn(v0);
            *(__half2*)(C + r1 * 128 + col) = __float22half2_rn(v1);
        } else {
            float* C = (float*)Cv;
            *(float2*)(C + r0 * 128 + col) = v0;
            *(float2*)(C + r1 * 128 + col) = v1;
        }
    }
}

// ---------------- attention: 2 warps per node (unchanged, R10-proven) ------
struct __align__(16) NodeSmem {
    __half dist[32 * 36];
    __half seq[32 * 20];
    float ud_t[32 * 8];
    float us_t[16 * 8];
    float c0[8];
    float lgk[32 * 10];
    float sd[2][256];
    float ss[2][128];
    float accp[2][128];
    int   jb[32];
};

__global__ __launch_bounds__(128) void attn_kernel(
    const float* __restrict__ dist_g, const float* __restrict__ seq_g,
    const int* __restrict__ idx, const float* __restrict__ qg,
    const __half* __restrict__ mkh, const __half* __restrict__ mvh,
    const float* __restrict__ Wk, const float* __restrict__ bk,
    const float* __restrict__ Wv, const float* __restrict__ bv,
    float* __restrict__ att_out)
{
    __shared__ NodeSmem S[2];
    const int lane = threadIdx.x & 31;
    const int w = threadIdx.x >> 5;
    const int half = w & 1;
    NodeSmem& s = S[w >> 1];
    const int n = blockIdx.x * 2 + (w >> 1);

    const float4 qv = ((const float4*)(qg + (long)n * 128))[lane];

    if (half == 0) {
        s.jb[lane] = idx[n * 32 + lane];
        const float4* dg = (const float4*)(dist_g + (long)n * 1024);
#pragma unroll
        for (int it = 0; it < 4; it++) {
            int i4 = it * 32 + lane;
            float4 v = dg[i4];
            uint2 h;
            h.x = h2u(__float22half2_rn(make_float2(v.x, v.y)));
            h.y = h2u(__float22half2_rn(make_float2(v.z, v.w)));
            *(uint2*)(s.dist + (i4 >> 3) * 36 + (i4 & 7) * 4) = h;
        }
    } else {
        const float4* dg = (const float4*)(dist_g + (long)n * 1024);
#pragma unroll
        for (int it = 4; it < 8; it++) {
            int i4 = it * 32 + lane;
            float4 v = dg[i4];
            uint2 h;
            h.x = h2u(__float22half2_rn(make_float2(v.x, v.y)));
            h.y = h2u(__float22half2_rn(make_float2(v.z, v.w)));
            *(uint2*)(s.dist + (i4 >> 3) * 36 + (i4 & 7) * 4) = h;
        }
        const float4* sg = (const float4*)(seq_g + (long)n * 512);
#pragma unroll
        for (int it = 0; it < 4; it++) {
            int i4 = it * 32 + lane;
            float4 v = sg[i4];
            uint2 h;
            h.x = h2u(__float22half2_rn(make_float2(v.x, v.y)));
            h.y = h2u(__float22half2_rn(make_float2(v.z, v.w)));
            *(uint2*)(s.seq + (i4 >> 2) * 20 + (i4 & 3) * 4) = h;
        }
    }

    const int h4 = lane >> 2;
#pragma unroll 8
    for (int rr = 0; rr < 24; rr++) {
        int r = half * 24 + rr;
        float4 wv = *(const float4*)(Wk + (long)(128 + r) * 128 + lane * 4);
        float p = wv.x * qv.x + wv.y * qv.y + wv.z * qv.z + wv.w * qv.w;
        p += __shfl_xor_sync(~0u, p, 1);
        p += __shfl_xor_sync(~0u, p, 2);
        if ((lane & 3) == 0) {
            if (r < 32) s.ud_t[r * 8 + h4] = p;
            else        s.us_t[(r - 32) * 8 + h4] = p;
        }
    }
    if (half == 0) {
        float4 wv = *(const float4*)(bk + lane * 4);
        float p = wv.x * qv.x + wv.y * qv.y + wv.z * qv.z + wv.w * qv.w;
        p += __shfl_xor_sync(~0u, p, 1);
        p += __shfl_xor_sync(~0u, p, 2);
        if ((lane & 3) == 0) s.c0[h4] = p;
    }
    __syncthreads();

#pragma unroll 8
    for (int kk = 0; kk < 16; kk++) {
        int k = half * 16 + kk;
        int j = s.jb[k];
        uint2 mr = *(const uint2*)(mkh + (long)j * 128 + lane * 4);
        float2 f0 = __half22float2(*(__half2*)&mr.x);
        float2 f1 = __half22float2(*(__half2*)&mr.y);
        float p = f0.x * qv.x + f0.y * qv.y + f1.x * qv.z + f1.y * qv.w;
        p += __shfl_xor_sync(~0u, p, 1);
        p += __shfl_xor_sync(~0u, p, 2);
        if ((lane & 3) == 0) s.lgk[k * 10 + h4] = p;
    }
    __syncthreads();

    {
        ull acc01 = 0ull, acc23 = 0ull;
        const __half* drow = s.dist + lane * 36;
#pragma unroll
        for (int i = 0; i < 8; i++) {
            uint2 hv = *(const uint2*)(drow + i * 4);
            float2 f0 = __half22float2(*(__half2*)&hv.x);
            float2 f1 = __half22float2(*(__half2*)&hv.y);
            float dv[4] = {f0.x, f0.y, f1.x, f1.y};
#pragma unroll
            for (int e = 0; e < 4; e++) {
                int d = i * 4 + e;
                ull dv2 = pack2(dv[e], dv[e]);
                const ull* u = (const ull*)(s.ud_t + d * 8 + half * 4);
                acc01 = ffma2(u[0], dv2, acc01);
                acc23 = ffma2(u[1], dv2, acc23);
            }
        }
        const __half* srow = s.seq + lane * 20;
#pragma unroll
        for (int i = 0; i < 4; i++) {
            uint2 hv = *(const uint2*)(srow + i * 4);
            float2 f0 = __half22float2(*(__half2*)&hv.x);
            float2 f1 = __half22float2(*(__half2*)&hv.y);
            float sv[4] = {f0.x, f0.y, f1.x, f1.y};
#pragma unroll
            for (int e = 0; e < 4; e++) {
                int si = i * 4 + e;
                ull sv2 = pack2(sv[e], sv[e]);
                const ull* u = (const ull*)(s.us_t + si * 8 + half * 4);
                acc01 = ffma2(u[0], sv2, acc01);
                acc23 = ffma2(u[1], sv2, acc23);
            }
        }
        float2 pA = unpack2(acc01), pB = unpack2(acc23);
        float pa[4] = {pA.x, pA.y, pB.x, pB.y};
#pragma unroll
        for (int hh = 0; hh < 4; hh++) {
            int h = half * 4 + hh;
            float lg = 0.25f * (s.lgk[lane * 10 + h] + pa[hh] + s.c0[h]);
            float m = lg;
#pragma unroll
            for (int o = 16; o > 0; o >>= 1)
                m = fmaxf(m, __shfl_xor_sync(~0u, m, o));
            float e = __expf(lg - m);
            float sm = e;
#pragma unroll
            for (int o = 16; o > 0; o >>= 1)
                sm += __shfl_xor_sync(~0u, sm, o);
            s.lgk[lane * 10 + h] = e / sm;
        }
    }
    __syncthreads();

    {
        const int sidx = lane & 15;
        float4 acc = make_float4(0.f, 0.f, 0.f, 0.f);
        ull sdl2[4] = {0ull, 0ull, 0ull, 0ull};
        float ssl[4] = {0.f, 0.f, 0.f, 0.f};
#pragma unroll 4
        for (int kk = 0; kk < 16; kk++) {
            int k = half * 16 + kk;
            int j = s.jb[k];
            float a = s.lgk[k * 10 + h4];
            uint2 mr = *(const uint2*)(mvh + (long)j * 128 + lane * 4);
            float2 f0 = __half22float2(*(__half2*)&mr.x);
            float2 f1 = __half22float2(*(__half2*)&mr.y);
            acc.x += a * f0.x; acc.y += a * f0.y;
            acc.z += a * f1.x; acc.w += a * f1.y;
            float dv = __half2float(s.dist[k * 36 + lane]);
            ull dv2 = pack2(dv, dv);
            const ull* ap = (const ull*)(s.lgk + k * 10);
#pragma unroll
            for (int r = 0; r < 4; r++) sdl2[r] = ffma2(ap[r], dv2, sdl2[r]);
            float sv = __half2float(s.seq[k * 20 + sidx]);
#pragma unroll
            for (int r = 0; r < 4; r++) {
                int h2 = (lane >> 4) + 2 * r;
                ssl[r] += s.lgk[k * 10 + h2] * sv;
            }
        }
        *(float4*)(s.accp[half] + lane * 4) = acc;
#pragma unroll
        for (int r = 0; r < 4; r++) {
            float2 p = unpack2(sdl2[r]);
            s.sd[half][(2 * r) * 32 + lane] = p.x;
            s.sd[half][(2 * r + 1) * 32 + lane] = p.y;
        }
#pragma unroll
        for (int r = 0; r < 4; r++) s.ss[half][lane + 32 * r] = ssl[r];
    }
    __syncthreads();

    {
        const int i0 = half * 64 + lane * 2;
        const int h = i0 >> 4;
        float2 a0 = *(const float2*)(s.accp[0] + i0);
        float2 a1 = *(const float2*)(s.accp[1] + i0);
        float2 bb = *(const float2*)(bv + i0);
        ull o = pack2(a0.x + a1.x + bb.x, a0.y + a1.y + bb.y);
#pragma unroll 8
        for (int d = 0; d < 32; d++) {
            float sdv = s.sd[0][h * 32 + d] + s.sd[1][h * 32 + d];
            ull wv = *(const ull*)(Wv + (long)(128 + d) * 128 + i0);
            o = ffma2(wv, pack2(sdv, sdv), o);
        }
#pragma unroll 8
        for (int j2 = 0; j2 < 16; j2++) {
            int si = (h & 1) * 16 + j2 + 32 * (h >> 1);
            float ssv = s.ss[0][si] + s.ss[1][si];
            ull wv = *(const ull*)(Wv + (long)(160 + j2) * 128 + i0);
            o = ffma2(wv, pack2(ssv, ssv), o);
        }
        float2 po = unpack2(o);
        *(float2*)(att_out + (long)n * 128 + i0) = po;
    }
}

// ---------------- launch ----------------
#define TG_SMEM ((32 + 128) * KPAD * 2)   // 43520 B < 48KB default

extern "C" void kernel_launch(void* const* d_in, const int* in_sizes, int n_in,
                              void* d_out, int out_size)
{
    const float* features = (const float*)d_in[0];
    const float* distances = (const float*)d_in[1];
    const float* sequence = (const float*)d_in[2];
    const float* encoder = (const float*)d_in[3];
    const int*   idx = (const int*)d_in[4];
    const float* W1 = (const float*)d_in[5];
    const float* b1 = (const float*)d_in[6];
    const float* W2 = (const float*)d_in[7];
    const float* b2 = (const float*)d_in[8];
    const float* W3 = (const float*)d_in[9];
    const float* b3 = (const float*)d_in[10];
    const float* Wq = (const float*)d_in[11];
    const float* bq = (const float*)d_in[12];
    const float* Wk = (const float*)d_in[13];
    const float* bk = (const float*)d_in[14];
    const float* Wv = (const float*)d_in[15];
    const float* bv = (const float*)d_in[16];
    const float* Wo = (const float*)d_in[17];
    const float* bo = (const float*)d_in[18];

    float *h1, *h2, *msg, *q, *att;
    __half *mk, *mv;
    cudaGetSymbolAddress((void**)&h1, g_h1);
    cudaGetSymbolAddress((void**)&h2, g_h2);
    cudaGetSymbolAddress((void**)&msg, g_msg);
    cudaGetSymbolAddress((void**)&q, g_q);
    cudaGetSymbolAddress((void**)&mk, g_mk);
    cudaGetSymbolAddress((void**)&mv, g_mv);
    cudaGetSymbolAddress((void**)&att, g_att);

    const int gb = N_NODES / 32;  // 512 blocks
    // h1 = relu(relu(F)@W1 + b1)
    tgemm<1,1,1,0,0><<<gb, 256, TG_SMEM>>>(features, W1, b1, nullptr, h1);
    // q = F@Wq + bq
    tgemm<0,0,1,0,0><<<gb, 256, TG_SMEM>>>(features, Wq, bq, nullptr, q);
    // h2 = relu(h1@W2 + b2)
    tgemm<0,1,1,0,0><<<gb, 256, TG_SMEM>>>(h1, W2, b2, nullptr, h2);
    // msg = relu(h2@W3 + b3) + encoder
    tgemm<0,1,1,1,0><<<gb, 256, TG_SMEM>>>(h2, W3, b3, encoder, msg);
    // mk = msg@Wk[:128] (fp16 out), mv = msg@Wv[:128]
    tgemm<0,0,0,0,1><<<gb, 256, TG_SMEM>>>(msg, Wk, nullptr, nullptr, mk);
    tgemm<0,0,0,0,1><<<gb, 256, TG_SMEM>>>(msg, Wv, nullptr, nullptr, mv);
    // attention (unchanged)
    attn_kernel<<<N_NODES / 2, 128>>>(distances, sequence, idx,
                                      q, mk, mv, Wk, bk, Wv, bv, att);
    // out = features + att@Wo + bo
    tgemm<0,0,1,1,0><<<gb, 256, TG_SMEM>>>(att, Wo, bo, features, (float*)d_out);
}

// round 13
// speedup vs baseline: 1.4823x; 1.0643x over previous
#include <cuda_runtime.h>
#include <cuda_fp16.h>

#define N_NODES 16384
#define SZ 128
#define KPAD 136   // halfs per smem row: 272B, 16B-aligned, conflict-free ldsm
typedef unsigned long long ull;
typedef unsigned int uint32;

__device__ __forceinline__ ull ffma2(ull a, ull b, ull c) {
    ull d;
    asm("fma.rn.f32x2 %0, %1, %2, %3;" : "=l"(d) : "l"(a), "l"(b), "l"(c));
    return d;
}
__device__ __forceinline__ ull pack2(float x, float y) {
    ull d;
    asm("mov.b64 %0, {%1, %2};" : "=l"(d) : "f"(x), "f"(y));
    return d;
}
__device__ __forceinline__ float2 unpack2(ull v) {
    float2 r;
    asm("mov.b64 {%0, %1}, %2;" : "=f"(r.x), "=f"(r.y) : "l"(v));
    return r;
}
__device__ __forceinline__ unsigned h2u(__half2 h) { return *(unsigned*)&h; }

__device__ __forceinline__ void ldsm_x4(uint32& r0, uint32& r1, uint32& r2,
                                        uint32& r3, uint32 addr) {
    asm volatile("ldmatrix.sync.aligned.m8n8.x4.shared.b16 {%0,%1,%2,%3}, [%4];"
                 : "=r"(r0), "=r"(r1), "=r"(r2), "=r"(r3) : "r"(addr));
}
__device__ __forceinline__ void ldsm_x2t(uint32& r0, uint32& r1, uint32 addr) {
    asm volatile("ldmatrix.sync.aligned.m8n8.x2.trans.shared.b16 {%0,%1}, [%2];"
                 : "=r"(r0), "=r"(r1) : "r"(addr));
}
__device__ __forceinline__ void mma_f16(float* c, uint32 a0, uint32 a1,
                                        uint32 a2, uint32 a3,
                                        uint32 b0, uint32 b1) {
    asm volatile(
        "mma.sync.aligned.m16n8k16.row.col.f32.f16.f16.f32 "
        "{%0,%1,%2,%3}, {%4,%5,%6,%7}, {%8,%9}, {%0,%1,%2,%3};"
        : "+f"(c[0]), "+f"(c[1]), "+f"(c[2]), "+f"(c[3])
        : "r"(a0), "r"(a1), "r"(a2), "r"(a3), "r"(b0), "r"(b1));
}

// ---------------- scratch ----------------
__device__ float  g_q[N_NODES * SZ];
__device__ __half g_mk[N_NODES * SZ];
__device__ __half g_mv[N_NODES * SZ];
__device__ float  g_att[N_NODES * SZ];

// ---------------- shared building blocks ----------------
__device__ __forceinline__ void stage_W_f16(const float* __restrict__ W,
                                            __half* Ws, int t) {
#pragma unroll
    for (int i = 0; i < 16; i++) {
        int idx = t + i * 256;
        int r = idx >> 5, c4 = idx & 31;
        float4 v = *(const float4*)(W + r * 128 + c4 * 4);
        uint2 pkt = make_uint2(h2u(__float22half2_rn(make_float2(v.x, v.y))),
                               h2u(__float22half2_rn(make_float2(v.z, v.w))));
        *(uint2*)(Ws + r * KPAD + c4 * 4) = pkt;
    }
}

__device__ __forceinline__ void tile_mma(uint32 a_base, uint32 w_base,
                                         uint32 a_off, uint32 b_krow,
                                         int nc0, float acc[4][4]) {
#pragma unroll
    for (int nt = 0; nt < 4; nt++)
#pragma unroll
        for (int c = 0; c < 4; c++) acc[nt][c] = 0.f;
#pragma unroll
    for (int ks = 0; ks < 8; ks++) {
        const int k0 = ks * 16;
        uint32 a0, a1, a2, a3;
        ldsm_x4(a0, a1, a2, a3, a_base + a_off + k0 * 2);
        uint32 baddr = w_base + ((k0 + b_krow) * KPAD + nc0) * 2;
#pragma unroll
        for (int nt = 0; nt < 4; nt++) {
            uint32 b0, b1;
            ldsm_x2t(b0, b1, baddr + nt * 16);
            mma_f16(acc[nt], a0, a1, a2, a3, b0, b1);
        }
    }
}

// epilogue -> smem fp16 tile (next-stage input). ADD: += addg row (fp32 gmem)
template <int RELU, int ADD>
__device__ __forceinline__ void epi_smem(float acc[4][4],
    const float* __restrict__ bias, const float* __restrict__ addg,
    long row0, __half* dst, int ar, int nc0, int lane)
{
    const int g = lane >> 2, tig = lane & 3;
#pragma unroll
    for (int nt = 0; nt < 4; nt++) {
        int col = nc0 + nt * 8 + tig * 2;
        float2 bz = *(const float2*)(bias + col);
        float2 v0 = make_float2(acc[nt][0] + bz.x, acc[nt][1] + bz.y);
        float2 v1 = make_float2(acc[nt][2] + bz.x, acc[nt][3] + bz.y);
        if (RELU) {
            v0.x = fmaxf(v0.x, 0.f); v0.y = fmaxf(v0.y, 0.f);
            v1.x = fmaxf(v1.x, 0.f); v1.y = fmaxf(v1.y, 0.f);
        }
        if (ADD) {
            float2 q0 = *(const float2*)(addg + (row0 + ar + g) * 128 + col);
            float2 q1 = *(const float2*)(addg + (row0 + ar + 8 + g) * 128 + col);
            v0.x += q0.x; v0.y += q0.y;
            v1.x += q1.x; v1.y += q1.y;
        }
        *(__half2*)(dst + (ar + g) * KPAD + col) = __float22half2_rn(v0);
        *(__half2*)(dst + (ar + 8 + g) * KPAD + col) = __float22half2_rn(v1);
    }
}

// epilogue -> gmem fp16 (no bias)
__device__ __forceinline__ void epi_gmem_h(float acc[4][4], long row0,
                                           __half* __restrict__ C,
                                           int ar, int nc0, int lane)
{
    const int g = lane >> 2, tig = lane & 3;
#pragma unroll
    for (int nt = 0; nt < 4; nt++) {
        int col = nc0 + nt * 8 + tig * 2;
        long r0 = row0 + ar + g, r1 = r0 + 8;
        *(__half2*)(C + r0 * 128 + col) =
            __float22half2_rn(make_float2(acc[nt][0], acc[nt][1]));
        *(__half2*)(C + r1 * 128 + col) =
            __float22half2_rn(make_float2(acc[nt][2], acc[nt][3]));
    }
}

// ---------------- MEGA kernel: F -> h1 -> h2 -> msg -> {mk, mv} ------------
// One block owns 32 rows through the whole chain; intermediates never touch
// DRAM. Smem: A0/A1 ping-pong (fp16 tiles) + one reloadable W buffer.
__global__ __launch_bounds__(256) void mlp_fused(
    const float* __restrict__ F,
    const float* __restrict__ W1, const float* __restrict__ b1,
    const float* __restrict__ W2, const float* __restrict__ b2,
    const float* __restrict__ W3, const float* __restrict__ b3,
    const float* __restrict__ enc,
    const float* __restrict__ Wk, const float* __restrict__ Wv,
    __half* __restrict__ mk, __half* __restrict__ mv)
{
    extern __shared__ __half sm[];
    __half* A0 = sm;                  // [32][KPAD]
    __half* A1 = sm + 32 * KPAD;      // [32][KPAD]
    __half* Ws = sm + 64 * KPAD;      // [128][KPAD]
    const int t = threadIdx.x;
    const int lane = t & 31, w = t >> 5;
    const int mw = w & 1, nw = w >> 1;
    const long row0 = (long)blockIdx.x * 32;
    const int ar = mw * 16, nc0 = nw * 32;

    const uint32 a0_base = (uint32)__cvta_generic_to_shared(A0);
    const uint32 a1_base = (uint32)__cvta_generic_to_shared(A1);
    const uint32 w_base = (uint32)__cvta_generic_to_shared(Ws);
    const int lrow = lane & 7, quad = lane >> 3;
    const uint32 a_off =
        ((uint32)(ar + lrow + ((quad & 1) << 3)) * KPAD + ((quad & 2) << 2)) * 2;
    const uint32 b_krow = (lane & 7) + (lane & 8);

    float acc[4][4];

    // ---- stage A0 = relu(F) tile + Ws = W1
#pragma unroll
    for (int i = 0; i < 4; i++) {
        int idx = t + i * 256;
        int r = idx >> 5, c4 = idx & 31;
        float4 v = *(const float4*)(F + (row0 + r) * 128 + c4 * 4);
        v.x = fmaxf(v.x, 0.f); v.y = fmaxf(v.y, 0.f);
        v.z = fmaxf(v.z, 0.f); v.w = fmaxf(v.w, 0.f);
        uint2 pkt = make_uint2(h2u(__float22half2_rn(make_float2(v.x, v.y))),
                               h2u(__float22half2_rn(make_float2(v.z, v.w))));
        *(uint2*)(A0 + r * KPAD + c4 * 4) = pkt;
    }
    stage_W_f16(W1, Ws, t);
    __syncthreads();

    // ---- h1 = relu(A0 @ W1 + b1) -> A1
    tile_mma(a0_base, w_base, a_off, b_krow, nc0, acc);
    epi_smem<1, 0>(acc, b1, nullptr, row0, A1, ar, nc0, lane);
    __syncthreads();

    // ---- h2 = relu(A1 @ W2 + b2) -> A0
    stage_W_f16(W2, Ws, t);
    __syncthreads();
    tile_mma(a1_base, w_base, a_off, b_krow, nc0, acc);
    epi_smem<1, 0>(acc, b2, nullptr, row0, A0, ar, nc0, lane);
    __syncthreads();

    // ---- msg = relu(A0 @ W3 + b3) + enc -> A1
    stage_W_f16(W3, Ws, t);
    __syncthreads();
    tile_mma(a0_base, w_base, a_off, b_krow, nc0, acc);
    epi_smem<1, 1>(acc, b3, enc, row0, A1, ar, nc0, lane);
    __syncthreads();

    // ---- mk = A1 @ Wk[:128] -> gmem (fp16)
    stage_W_f16(Wk, Ws, t);
    __syncthreads();
    tile_mma(a1_base, w_base, a_off, b_krow, nc0, acc);
    epi_gmem_h(acc, row0, mk, ar, nc0, lane);
    __syncthreads();

    // ---- mv = A1 @ Wv[:128] -> gmem (fp16)
    stage_W_f16(Wv, Ws, t);
    __syncthreads();
    tile_mma(a1_base, w_base, a_off, b_krow, nc0, acc);
    epi_gmem_h(acc, row0, mv, ar, nc0, lane);
}

// ------- fp16 tensor-core GEMM (R12-proven): used for q and out-projection
template <int RELU_IN, int RELU_OUT, int HAS_BIAS, int HAS_ADD, int OUT_HALF>
__global__ __launch_bounds__(256) void tgemm(
    const float* __restrict__ A, const float* __restrict__ W,
    const float* __restrict__ bias, const float* __restrict__ add,
    void* __restrict__ Cv)
{
    extern __shared__ __half sm[];
    __half* As = sm;
    __half* Ws = sm + 32 * KPAD;
    const int t = threadIdx.x;
    const int lane = t & 31, w = t >> 5;
    const int mw = w & 1, nw = w >> 1;
    const long row0 = (long)blockIdx.x * 32;

#pragma unroll
    for (int i = 0; i < 4; i++) {
        int idx = t + i * 256;
        int r = idx >> 5, c4 = idx & 31;
        float4 v = *(const float4*)(A + (row0 + r) * 128 + c4 * 4);
        if (RELU_IN) {
            v.x = fmaxf(v.x, 0.f); v.y = fmaxf(v.y, 0.f);
            v.z = fmaxf(v.z, 0.f); v.w = fmaxf(v.w, 0.f);
        }
        uint2 pkt = make_uint2(h2u(__float22half2_rn(make_float2(v.x, v.y))),
                               h2u(__float22half2_rn(make_float2(v.z, v.w))));
        *(uint2*)(As + r * KPAD + c4 * 4) = pkt;
    }
    stage_W_f16(W, Ws, t);
    __syncthreads();

    const int ar = mw * 16, nc0 = nw * 32;
    const uint32 a_base = (uint32)__cvta_generic_to_shared(As);
    const uint32 w_base = (uint32)__cvta_generic_to_shared(Ws);
    const int lrow = lane & 7, quad = lane >> 3;
    const uint32 a_off =
        ((uint32)(ar + lrow + ((quad & 1) << 3)) * KPAD + ((quad & 2) << 2)) * 2;
    const uint32 b_krow = (lane & 7) + (lane & 8);

    float acc[4][4];
    tile_mma(a_base, w_base, a_off, b_krow, nc0, acc);

    const int g = lane >> 2, tig = lane & 3;
#pragma unroll
    for (int nt = 0; nt < 4; nt++) {
        int col = nc0 + nt * 8 + tig * 2;
        long r0 = row0 + ar + g;
        long r1 = r0 + 8;
        float2 bz = make_float2(0.f, 0.f);
        if (HAS_BIAS) bz = *(const float2*)(bias + col);
        float2 v0 = make_float2(acc[nt][0] + bz.x, acc[nt][1] + bz.y);
        float2 v1 = make_float2(acc[nt][2] + bz.x, acc[nt][3] + bz.y);
        if (RELU_OUT) {
            v0.x = fmaxf(v0.x, 0.f); v0.y = fmaxf(v0.y, 0.f);
            v1.x = fmaxf(v1.x, 0.f); v1.y = fmaxf(v1.y, 0.f);
        }
        if (HAS_ADD) {
            float2 q0 = *(const float2*)(add + r0 * 128 + col);
            float2 q1 = *(const float2*)(add + r1 * 128 + col);
            v0.x += q0.x; v0.y += q0.y;
            v1.x += q1.x; v1.y += q1.y;
        }
        if (OUT_HALF) {
            __half* C = (__half*)Cv;
            *(__half2*)(C + r0 * 128 + col) = __float22half2_rn(v0);
            *(__half2*)(C + r1 * 128 + col) = __float22half2_rn(v1);
        } else {
            float* C = (float*)Cv;
            *(float2*)(C + r0 * 128 + col) = v0;
            *(float2*)(C + r1 * 128 + col) = v1;
        }
    }
}

// ---------------- attention: 2 warps per node (unchanged, R10-proven) ------
struct __align__(16) NodeSmem {
    __half dist[32 * 36];
    __half seq[32 * 20];
    float ud_t[32 * 8];
    float us_t[16 * 8];
    float c0[8];
    float lgk[32 * 10];
    float sd[2][256];
    float ss[2][128];
    float accp[2][128];
    int   jb[32];
};

__global__ __launch_bounds__(128) void attn_kernel(
    const float* __restrict__ dist_g, const float* __restrict__ seq_g,
    const int* __restrict__ idx, const float* __restrict__ qg,
    const __half* __restrict__ mkh, const __half* __restrict__ mvh,
    const float* __restrict__ Wk, const float* __restrict__ bk,
    const float* __restrict__ Wv, const float* __restrict__ bv,
    float* __restrict__ att_out)
{
    __shared__ NodeSmem S[2];
    const int lane = threadIdx.x & 31;
    const int w = threadIdx.x >> 5;
    const int half = w & 1;
    NodeSmem& s = S[w >> 1];
    const int n = blockIdx.x * 2 + (w >> 1);

    const float4 qv = ((const float4*)(qg + (long)n * 128))[lane];

    if (half == 0) {
        s.jb[lane] = idx[n * 32 + lane];
        const float4* dg = (const float4*)(dist_g + (long)n * 1024);
#pragma unroll
        for (int it = 0; it < 4; it++) {
            int i4 = it * 32 + lane;
            float4 v = dg[i4];
            uint2 h;
            h.x = h2u(__float22half2_rn(make_float2(v.x, v.y)));
            h.y = h2u(__float22half2_rn(make_float2(v.z, v.w)));
            *(uint2*)(s.dist + (i4 >> 3) * 36 + (i4 & 7) * 4) = h;
        }
    } else {
        const float4* dg = (const float4*)(dist_g + (long)n * 1024);
#pragma unroll
        for (int it = 4; it < 8; it++) {
            int i4 = it * 32 + lane;
            float4 v = dg[i4];
            uint2 h;
            h.x = h2u(__float22half2_rn(make_float2(v.x, v.y)));
            h.y = h2u(__float22half2_rn(make_float2(v.z, v.w)));
            *(uint2*)(s.dist + (i4 >> 3) * 36 + (i4 & 7) * 4) = h;
        }
        const float4* sg = (const float4*)(seq_g + (long)n * 512);
#pragma unroll
        for (int it = 0; it < 4; it++) {
            int i4 = it * 32 + lane;
            float4 v = sg[i4];
            uint2 h;
            h.x = h2u(__float22half2_rn(make_float2(v.x, v.y)));
            h.y = h2u(__float22half2_rn(make_float2(v.z, v.w)));
            *(uint2*)(s.seq + (i4 >> 2) * 20 + (i4 & 3) * 4) = h;
        }
    }

    const int h4 = lane >> 2;
#pragma unroll 8
    for (int rr = 0; rr < 24; rr++) {
        int r = half * 24 + rr;
        float4 wv = *(const float4*)(Wk + (long)(128 + r) * 128 + lane * 4);
        float p = wv.x * qv.x + wv.y * qv.y + wv.z * qv.z + wv.w * qv.w;
        p += __shfl_xor_sync(~0u, p, 1);
        p += __shfl_xor_sync(~0u, p, 2);
        if ((lane & 3) == 0) {
            if (r < 32) s.ud_t[r * 8 + h4] = p;
            else        s.us_t[(r - 32) * 8 + h4] = p;
        }
    }
    if (half == 0) {
        float4 wv = *(const float4*)(bk + lane * 4);
        float p = wv.x * qv.x + wv.y * qv.y + wv.z * qv.z + wv.w * qv.w;
        p += __shfl_xor_sync(~0u, p, 1);
        p += __shfl_xor_sync(~0u, p, 2);
        if ((lane & 3) == 0) s.c0[h4] = p;
    }
    __syncthreads();

#pragma unroll 8
    for (int kk = 0; kk < 16; kk++) {
        int k = half * 16 + kk;
        int j = s.jb[k];
        uint2 mr = *(const uint2*)(mkh + (long)j * 128 + lane * 4);
        float2 f0 = __half22float2(*(__half2*)&mr.x);
        float2 f1 = __half22float2(*(__half2*)&mr.y);
        float p = f0.x * qv.x + f0.y * qv.y + f1.x * qv.z + f1.y * qv.w;
        p += __shfl_xor_sync(~0u, p, 1);
        p += __shfl_xor_sync(~0u, p, 2);
        if ((lane & 3) == 0) s.lgk[k * 10 + h4] = p;
    }
    __syncthreads();

    {
        ull acc01 = 0ull, acc23 = 0ull;
        const __half* drow = s.dist + lane * 36;
#pragma unroll
        for (int i = 0; i < 8; i++) {
            uint2 hv = *(const uint2*)(drow + i * 4);
            float2 f0 = __half22float2(*(__half2*)&hv.x);
            float2 f1 = __half22float2(*(__half2*)&hv.y);
            float dv[4] = {f0.x, f0.y, f1.x, f1.y};
#pragma unroll
            for (int e = 0; e < 4; e++) {
                int d = i * 4 + e;
                ull dv2 = pack2(dv[e], dv[e]);
                const ull* u = (const ull*)(s.ud_t + d * 8 + half * 4);
                acc01 = ffma2(u[0], dv2, acc01);
                acc23 = ffma2(u[1], dv2, acc23);
            }
        }
        const __half* srow = s.seq + lane * 20;
#pragma unroll
        for (int i = 0; i < 4; i++) {
            uint2 hv = *(const uint2*)(srow + i * 4);
            float2 f0 = __half22float2(*(__half2*)&hv.x);
            float2 f1 = __half22float2(*(__half2*)&hv.y);
            float sv[4] = {f0.x, f0.y, f1.x, f1.y};
#pragma unroll
            for (int e = 0; e < 4; e++) {
                int si = i * 4 + e;
                ull sv2 = pack2(sv[e], sv[e]);
                const ull* u = (const ull*)(s.us_t + si * 8 + half * 4);
                acc01 = ffma2(u[0], sv2, acc01);
                acc23 = ffma2(u[1], sv2, acc23);
            }
        }
        float2 pA = unpack2(acc01), pB = unpack2(acc23);
        float pa[4] = {pA.x, pA.y, pB.x, pB.y};
#pragma unroll
        for (int hh = 0; hh < 4; hh++) {
            int h = half * 4 + hh;
            float lg = 0.25f * (s.lgk[lane * 10 + h] + pa[hh] + s.c0[h]);
            float m = lg;
#pragma unroll
            for (int o = 16; o > 0; o >>= 1)
                m = fmaxf(m, __shfl_xor_sync(~0u, m, o));
            float e = __expf(lg - m);
            float sm = e;
#pragma unroll
            for (int o = 16; o > 0; o >>= 1)
                sm += __shfl_xor_sync(~0u, sm, o);
            s.lgk[lane * 10 + h] = e / sm;
        }
    }
    __syncthreads();

    {
        const int sidx = lane & 15;
        float4 acc = make_float4(0.f, 0.f, 0.f, 0.f);
        ull sdl2[4] = {0ull, 0ull, 0ull, 0ull};
        float ssl[4] = {0.f, 0.f, 0.f, 0.f};
#pragma unroll 4
        for (int kk = 0; kk < 16; kk++) {
            int k = half * 16 + kk;
            int j = s.jb[k];
            float a = s.lgk[k * 10 + h4];
            uint2 mr = *(const uint2*)(mvh + (long)j * 128 + lane * 4);
            float2 f0 = __half22float2(*(__half2*)&mr.x);
            float2 f1 = __half22float2(*(__half2*)&mr.y);
            acc.x += a * f0.x; acc.y += a * f0.y;
            acc.z += a * f1.x; acc.w += a * f1.y;
            float dv = __half2float(s.dist[k * 36 + lane]);
            ull dv2 = pack2(dv, dv);
            const ull* ap = (const ull*)(s.lgk + k * 10);
#pragma unroll
            for (int r = 0; r < 4; r++) sdl2[r] = ffma2(ap[r], dv2, sdl2[r]);
            float sv = __half2float(s.seq[k * 20 + sidx]);
#pragma unroll
            for (int r = 0; r < 4; r++) {
                int h2 = (lane >> 4) + 2 * r;
                ssl[r] += s.lgk[k * 10 + h2] * sv;
            }
        }
        *(float4*)(s.accp[half] + lane * 4) = acc;
#pragma unroll
        for (int r = 0; r < 4; r++) {
            float2 p = unpack2(sdl2[r]);
            s.sd[half][(2 * r) * 32 + lane] = p.x;
            s.sd[half][(2 * r + 1) * 32 + lane] = p.y;
        }
#pragma unroll
        for (int r = 0; r < 4; r++) s.ss[half][lane + 32 * r] = ssl[r];
    }
    __syncthreads();

    {
        const int i0 = half * 64 + lane * 2;
        const int h = i0 >> 4;
        float2 a0 = *(const float2*)(s.accp[0] + i0);
        float2 a1 = *(const float2*)(s.accp[1] + i0);
        float2 bb = *(const float2*)(bv + i0);
        ull o = pack2(a0.x + a1.x + bb.x, a0.y + a1.y + bb.y);
#pragma unroll 8
        for (int d = 0; d < 32; d++) {
            float sdv = s.sd[0][h * 32 + d] + s.sd[1][h * 32 + d];
            ull wv = *(const ull*)(Wv + (long)(128 + d) * 128 + i0);
            o = ffma2(wv, pack2(sdv, sdv), o);
        }
#pragma unroll 8
        for (int j2 = 0; j2 < 16; j2++) {
            int si = (h & 1) * 16 + j2 + 32 * (h >> 1);
            float ssv = s.ss[0][si] + s.ss[1][si];
            ull wv = *(const ull*)(Wv + (long)(160 + j2) * 128 + i0);
            o = ffma2(wv, pack2(ssv, ssv), o);
        }
        float2 po = unpack2(o);
        *(float2*)(att_out + (long)n * 128 + i0) = po;
    }
}

// ---------------- launch ----------------
#define TG_SMEM ((32 + 128) * KPAD * 2)     // 43520 B
#define MEGA_SMEM ((32 + 32 + 128) * KPAD * 2)  // 52224 B

extern "C" void kernel_launch(void* const* d_in, const int* in_sizes, int n_in,
                              void* d_out, int out_size)
{
    const float* features = (const float*)d_in[0];
    const float* distances = (const float*)d_in[1];
    const float* sequence = (const float*)d_in[2];
    const float* encoder = (const float*)d_in[3];
    const int*   idx = (const int*)d_in[4];
    const float* W1 = (const float*)d_in[5];
    const float* b1 = (const float*)d_in[6];
    const float* W2 = (const float*)d_in[7];
    const float* b2 = (const float*)d_in[8];
    const float* W3 = (const float*)d_in[9];
    const float* b3 = (const float*)d_in[10];
    const float* Wq = (const float*)d_in[11];
    const float* bq = (const float*)d_in[12];
    const float* Wk = (const float*)d_in[13];
    const float* bk = (const float*)d_in[14];
    const float* Wv = (const float*)d_in[15];
    const float* bv = (const float*)d_in[16];
    const float* Wo = (const float*)d_in[17];
    const float* bo = (const float*)d_in[18];

    float *q, *att;
    __half *mk, *mv;
    cudaGetSymbolAddress((void**)&q, g_q);
    cudaGetSymbolAddress((void**)&mk, g_mk);
    cudaGetSymbolAddress((void**)&mv, g_mv);
    cudaGetSymbolAddress((void**)&att, g_att);

    static int smem_set = 0;
    if (!smem_set) {
        cudaFuncSetAttribute(mlp_fused,
            cudaFuncAttributeMaxDynamicSharedMemorySize, MEGA_SMEM);
        smem_set = 1;
    }

    const int gb = N_NODES / 32;  // 512 blocks
    // F -> h1 -> h2 -> msg -> {mk, mv}   (one kernel, no DRAM intermediates)
    mlp_fused<<<gb, 256, MEGA_SMEM>>>(features, W1, b1, W2, b2, W3, b3,
                                      encoder, Wk, Wv, mk, mv);
    // q = F@Wq + bq
    tgemm<0,0,1,0,0><<<gb, 256, TG_SMEM>>>(features, Wq, bq, nullptr, q);
    // attention
    attn_kernel<<<N_NODES / 2, 128>>>(distances, sequence, idx,
                                      q, mk, mv, Wk, bk, Wv, bv, att);
    // out = features + att@Wo + bo
    tgemm<0,0,1,1,0><<<gb, 256, TG_SMEM>>>(att, Wo, bo, features, (float*)d_out);
}

// round 14
// speedup vs baseline: 1.5858x; 1.0698x over previous
#include <cuda_runtime.h>
#include <cuda_fp16.h>

#define N_NODES 16384
#define SZ 128
#define KPAD 136   // halfs per smem row: 272B, 16B-aligned, conflict-free ldsm
typedef unsigned long long ull;
typedef unsigned int uint32;

__device__ __forceinline__ ull ffma2(ull a, ull b, ull c) {
    ull d;
    asm("fma.rn.f32x2 %0, %1, %2, %3;" : "=l"(d) : "l"(a), "l"(b), "l"(c));
    return d;
}
__device__ __forceinline__ ull pack2(float x, float y) {
    ull d;
    asm("mov.b64 %0, {%1, %2};" : "=l"(d) : "f"(x), "f"(y));
    return d;
}
__device__ __forceinline__ float2 unpack2(ull v) {
    float2 r;
    asm("mov.b64 {%0, %1}, %2;" : "=f"(r.x), "=f"(r.y) : "l"(v));
    return r;
}
__device__ __forceinline__ unsigned h2u(__half2 h) { return *(unsigned*)&h; }

__device__ __forceinline__ void ldsm_x4(uint32& r0, uint32& r1, uint32& r2,
                                        uint32& r3, uint32 addr) {
    asm volatile("ldmatrix.sync.aligned.m8n8.x4.shared.b16 {%0,%1,%2,%3}, [%4];"
                 : "=r"(r0), "=r"(r1), "=r"(r2), "=r"(r3) : "r"(addr));
}
__device__ __forceinline__ void ldsm_x2t(uint32& r0, uint32& r1, uint32 addr) {
    asm volatile("ldmatrix.sync.aligned.m8n8.x2.trans.shared.b16 {%0,%1}, [%2];"
                 : "=r"(r0), "=r"(r1) : "r"(addr));
}
__device__ __forceinline__ void mma_f16(float* c, uint32 a0, uint32 a1,
                                        uint32 a2, uint32 a3,
                                        uint32 b0, uint32 b1) {
    asm volatile(
        "mma.sync.aligned.m16n8k16.row.col.f32.f16.f16.f32 "
        "{%0,%1,%2,%3}, {%4,%5,%6,%7}, {%8,%9}, {%0,%1,%2,%3};"
        : "+f"(c[0]), "+f"(c[1]), "+f"(c[2]), "+f"(c[3])
        : "r"(a0), "r"(a1), "r"(a2), "r"(a3), "r"(b0), "r"(b1));
}

// ---------------- scratch ----------------
__device__ float  g_q[N_NODES * SZ];
__device__ __half g_mk[N_NODES * SZ];
__device__ __half g_mv[N_NODES * SZ];
__device__ float  g_att[N_NODES * SZ];

// ---------------- shared building blocks ----------------
__device__ __forceinline__ void stage_W_f16(const float* __restrict__ W,
                                            __half* Ws, int t) {
#pragma unroll
    for (int i = 0; i < 16; i++) {
        int idx = t + i * 256;
        int r = idx >> 5, c4 = idx & 31;
        float4 v = *(const float4*)(W + r * 128 + c4 * 4);
        uint2 pkt = make_uint2(h2u(__float22half2_rn(make_float2(v.x, v.y))),
                               h2u(__float22half2_rn(make_float2(v.z, v.w))));
        *(uint2*)(Ws + r * KPAD + c4 * 4) = pkt;
    }
}

__device__ __forceinline__ void tile_mma(uint32 a_base, uint32 w_base,
                                         uint32 a_off, uint32 b_krow,
                                         int nc0, float acc[4][4]) {
#pragma unroll
    for (int nt = 0; nt < 4; nt++)
#pragma unroll
        for (int c = 0; c < 4; c++) acc[nt][c] = 0.f;
#pragma unroll
    for (int ks = 0; ks < 8; ks++) {
        const int k0 = ks * 16;
        uint32 a0, a1, a2, a3;
        ldsm_x4(a0, a1, a2, a3, a_base + a_off + k0 * 2);
        uint32 baddr = w_base + ((k0 + b_krow) * KPAD + nc0) * 2;
#pragma unroll
        for (int nt = 0; nt < 4; nt++) {
            uint32 b0, b1;
            ldsm_x2t(b0, b1, baddr + nt * 16);
            mma_f16(acc[nt], a0, a1, a2, a3, b0, b1);
        }
    }
}

// epilogue -> smem fp16 tile. ADD: += addg row (fp32 gmem)
template <int RELU, int ADD>
__device__ __forceinline__ void epi_smem(float acc[4][4],
    const float* __restrict__ bias, const float* __restrict__ addg,
    long row0, __half* dst, int ar, int nc0, int lane)
{
    const int g = lane >> 2, tig = lane & 3;
#pragma unroll
    for (int nt = 0; nt < 4; nt++) {
        int col = nc0 + nt * 8 + tig * 2;
        float2 bz = *(const float2*)(bias + col);
        float2 v0 = make_float2(acc[nt][0] + bz.x, acc[nt][1] + bz.y);
        float2 v1 = make_float2(acc[nt][2] + bz.x, acc[nt][3] + bz.y);
        if (RELU) {
            v0.x = fmaxf(v0.x, 0.f); v0.y = fmaxf(v0.y, 0.f);
            v1.x = fmaxf(v1.x, 0.f); v1.y = fmaxf(v1.y, 0.f);
        }
        if (ADD) {
            float2 q0 = *(const float2*)(addg + (row0 + ar + g) * 128 + col);
            float2 q1 = *(const float2*)(addg + (row0 + ar + 8 + g) * 128 + col);
            v0.x += q0.x; v0.y += q0.y;
            v1.x += q1.x; v1.y += q1.y;
        }
        *(__half2*)(dst + (ar + g) * KPAD + col) = __float22half2_rn(v0);
        *(__half2*)(dst + (ar + 8 + g) * KPAD + col) = __float22half2_rn(v1);
    }
}

// epilogue -> gmem fp16 (no bias)
__device__ __forceinline__ void epi_gmem_h(float acc[4][4], long row0,
                                           __half* __restrict__ C,
                                           int ar, int nc0, int lane)
{
    const int g = lane >> 2, tig = lane & 3;
#pragma unroll
    for (int nt = 0; nt < 4; nt++) {
        int col = nc0 + nt * 8 + tig * 2;
        long r0 = row0 + ar + g, r1 = r0 + 8;
        *(__half2*)(C + r0 * 128 + col) =
            __float22half2_rn(make_float2(acc[nt][0], acc[nt][1]));
        *(__half2*)(C + r1 * 128 + col) =
            __float22half2_rn(make_float2(acc[nt][2], acc[nt][3]));
    }
}

// epilogue -> gmem fp32 with bias
__device__ __forceinline__ void epi_gmem_f(float acc[4][4],
    const float* __restrict__ bias, long row0, float* __restrict__ C,
    int ar, int nc0, int lane)
{
    const int g = lane >> 2, tig = lane & 3;
#pragma unroll
    for (int nt = 0; nt < 4; nt++) {
        int col = nc0 + nt * 8 + tig * 2;
        long r0 = row0 + ar + g, r1 = r0 + 8;
        float2 bz = *(const float2*)(bias + col);
        *(float2*)(C + r0 * 128 + col) =
            make_float2(acc[nt][0] + bz.x, acc[nt][1] + bz.y);
        *(float2*)(C + r1 * 128 + col) =
            make_float2(acc[nt][2] + bz.x, acc[nt][3] + bz.y);
    }
}

// ------- PERSISTENT MLP: all 6 weights staged ONCE in smem (226.3 KB) ------
// 128 blocks x 4 tiles each; per tile: q, h1, h2, msg, mk, mv — zero W traffic.
__global__ __launch_bounds__(256) void mlp_persistent(
    const float* __restrict__ F,
    const float* __restrict__ Wq, const float* __restrict__ bq,
    const float* __restrict__ W1, const float* __restrict__ b1,
    const float* __restrict__ W2, const float* __restrict__ b2,
    const float* __restrict__ W3, const float* __restrict__ b3,
    const float* __restrict__ enc,
    const float* __restrict__ Wk, const float* __restrict__ Wv,
    float* __restrict__ q, __half* __restrict__ mk, __half* __restrict__ mv)
{
    extern __shared__ __half sm[];
    __half* A0 = sm;                        // raw F tile -> later h1/msg chain
    __half* A1 = sm + 32 * KPAD;
    __half* WS = sm + 64 * KPAD;            // 6 x [128][KPAD]
    const int t = threadIdx.x;
    const int lane = t & 31, w = t >> 5;
    const int mw = w & 1, nw = w >> 1;
    const int ar = mw * 16, nc0 = nw * 32;

    const uint32 a0_base = (uint32)__cvta_generic_to_shared(A0);
    const uint32 a1_base = (uint32)__cvta_generic_to_shared(A1);
    const int lrow = lane & 7, quad = lane >> 3;
    const uint32 a_off =
        ((uint32)(ar + lrow + ((quad & 1) << 3)) * KPAD + ((quad & 2) << 2)) * 2;
    const uint32 b_krow = (lane & 7) + (lane & 8);

    // ---- stage all six weights once
    stage_W_f16(Wq, WS + 0 * 128 * KPAD, t);
    stage_W_f16(W1, WS + 1 * 128 * KPAD, t);
    stage_W_f16(W2, WS + 2 * 128 * KPAD, t);
    stage_W_f16(W3, WS + 3 * 128 * KPAD, t);
    stage_W_f16(Wk, WS + 4 * 128 * KPAD, t);
    stage_W_f16(Wv, WS + 5 * 128 * KPAD, t);
    uint32 wb[6];
#pragma unroll
    for (int i = 0; i < 6; i++)
        wb[i] = (uint32)__cvta_generic_to_shared(WS + i * 128 * KPAD);
    __syncthreads();

    float acc[4][4];
#pragma unroll 1
    for (int it = 0; it < 4; it++) {
        const long tile = blockIdx.x + 128 * it;   // 512 tiles total
        const long row0 = tile * 32;

        // stage A0 = raw F, A1 = relu(F)
#pragma unroll
        for (int i = 0; i < 4; i++) {
            int idx = t + i * 256;
            int r = idx >> 5, c4 = idx & 31;
            float4 v = *(const float4*)(F + (row0 + r) * 128 + c4 * 4);
            uint2 raw = make_uint2(
                h2u(__float22half2_rn(make_float2(v.x, v.y))),
                h2u(__float22half2_rn(make_float2(v.z, v.w))));
            *(uint2*)(A0 + r * KPAD + c4 * 4) = raw;
            v.x = fmaxf(v.x, 0.f); v.y = fmaxf(v.y, 0.f);
            v.z = fmaxf(v.z, 0.f); v.w = fmaxf(v.w, 0.f);
            uint2 rl = make_uint2(
                h2u(__float22half2_rn(make_float2(v.x, v.y))),
                h2u(__float22half2_rn(make_float2(v.z, v.w))));
            *(uint2*)(A1 + r * KPAD + c4 * 4) = rl;
        }
        __syncthreads();

        // q = A0 @ Wq + bq -> gmem fp32
        tile_mma(a0_base, wb[0], a_off, b_krow, nc0, acc);
        epi_gmem_f(acc, bq, row0, q, ar, nc0, lane);
        __syncthreads();                       // all A0 reads done

        // h1 = relu(A1 @ W1 + b1) -> A0
        tile_mma(a1_base, wb[1], a_off, b_krow, nc0, acc);
        epi_smem<1, 0>(acc, b1, nullptr, row0, A0, ar, nc0, lane);
        __syncthreads();

        // h2 = relu(A0 @ W2 + b2) -> A1
        tile_mma(a0_base, wb[2], a_off, b_krow, nc0, acc);
        epi_smem<1, 0>(acc, b2, nullptr, row0, A1, ar, nc0, lane);
        __syncthreads();

        // msg = relu(A1 @ W3 + b3) + enc -> A0
        tile_mma(a1_base, wb[3], a_off, b_krow, nc0, acc);
        epi_smem<1, 1>(acc, b3, enc, row0, A0, ar, nc0, lane);
        __syncthreads();

        // mk = A0 @ Wk[:128] -> gmem fp16 ; mv = A0 @ Wv[:128] -> gmem fp16
        tile_mma(a0_base, wb[4], a_off, b_krow, nc0, acc);
        epi_gmem_h(acc, row0, mk, ar, nc0, lane);
        tile_mma(a0_base, wb[5], a_off, b_krow, nc0, acc);
        epi_gmem_h(acc, row0, mv, ar, nc0, lane);
        __syncthreads();                       // before next tile overwrites A0/A1
    }
}

// ------- fp16 tensor-core GEMM (R12-proven): out-projection only ----------
template <int RELU_IN, int RELU_OUT, int HAS_BIAS, int HAS_ADD, int OUT_HALF>
__global__ __launch_bounds__(256) void tgemm(
    const float* __restrict__ A, const float* __restrict__ W,
    const float* __restrict__ bias, const float* __restrict__ add,
    void* __restrict__ Cv)
{
    extern __shared__ __half sm[];
    __half* As = sm;
    __half* Ws = sm + 32 * KPAD;
    const int t = threadIdx.x;
    const int lane = t & 31, w = t >> 5;
    const int mw = w & 1, nw = w >> 1;
    const long row0 = (long)blockIdx.x * 32;

#pragma unroll
    for (int i = 0; i < 4; i++) {
        int idx = t + i * 256;
        int r = idx >> 5, c4 = idx & 31;
        float4 v = *(const float4*)(A + (row0 + r) * 128 + c4 * 4);
        if (RELU_IN) {
            v.x = fmaxf(v.x, 0.f); v.y = fmaxf(v.y, 0.f);
            v.z = fmaxf(v.z, 0.f); v.w = fmaxf(v.w, 0.f);
        }
        uint2 pkt = make_uint2(h2u(__float22half2_rn(make_float2(v.x, v.y))),
                               h2u(__float22half2_rn(make_float2(v.z, v.w))));
        *(uint2*)(As + r * KPAD + c4 * 4) = pkt;
    }
    stage_W_f16(W, Ws, t);
    __syncthreads();

    const int ar = mw * 16, nc0 = nw * 32;
    const uint32 a_base = (uint32)__cvta_generic_to_shared(As);
    const uint32 w_base = (uint32)__cvta_generic_to_shared(Ws);
    const int lrow = lane & 7, quad = lane >> 3;
    const uint32 a_off =
        ((uint32)(ar + lrow + ((quad & 1) << 3)) * KPAD + ((quad & 2) << 2)) * 2;
    const uint32 b_krow = (lane & 7) + (lane & 8);

    float acc[4][4];
    tile_mma(a_base, w_base, a_off, b_krow, nc0, acc);

    const int g = lane >> 2, tig = lane & 3;
#pragma unroll
    for (int nt = 0; nt < 4; nt++) {
        int col = nc0 + nt * 8 + tig * 2;
        long r0 = row0 + ar + g;
        long r1 = r0 + 8;
        float2 bz = make_float2(0.f, 0.f);
        if (HAS_BIAS) bz = *(const float2*)(bias + col);
        float2 v0 = make_float2(acc[nt][0] + bz.x, acc[nt][1] + bz.y);
        float2 v1 = make_float2(acc[nt][2] + bz.x, acc[nt][3] + bz.y);
        if (RELU_OUT) {
            v0.x = fmaxf(v0.x, 0.f); v0.y = fmaxf(v0.y, 0.f);
            v1.x = fmaxf(v1.x, 0.f); v1.y = fmaxf(v1.y, 0.f);
        }
        if (HAS_ADD) {
            float2 q0 = *(const float2*)(add + r0 * 128 + col);
            float2 q1 = *(const float2*)(add + r1 * 128 + col);
            v0.x += q0.x; v0.y += q0.y;
            v1.x += q1.x; v1.y += q1.y;
        }
        if (OUT_HALF) {
            __half* C = (__half*)Cv;
            *(__half2*)(C + r0 * 128 + col) = __float22half2_rn(v0);
            *(__half2*)(C + r1 * 128 + col) = __float22half2_rn(v1);
        } else {
            float* C = (float*)Cv;
            *(float2*)(C + r0 * 128 + col) = v0;
            *(float2*)(C + r1 * 128 + col) = v1;
        }
    }
}

// ---------------- attention: 2 warps per node (unchanged, R10-proven) ------
struct __align__(16) NodeSmem {
    __half dist[32 * 36];
    __half seq[32 * 20];
    float ud_t[32 * 8];
    float us_t[16 * 8];
    float c0[8];
    float lgk[32 * 10];
    float sd[2][256];
    float ss[2][128];
    float accp[2][128];
    int   jb[32];
};

__global__ __launch_bounds__(128) void attn_kernel(
    const float* __restrict__ dist_g, const float* __restrict__ seq_g,
    const int* __restrict__ idx, const float* __restrict__ qg,
    const __half* __restrict__ mkh, const __half* __restrict__ mvh,
    const float* __restrict__ Wk, const float* __restrict__ bk,
    const float* __restrict__ Wv, const float* __restrict__ bv,
    float* __restrict__ att_out)
{
    __shared__ NodeSmem S[2];
    const int lane = threadIdx.x & 31;
    const int w = threadIdx.x >> 5;
    const int half = w & 1;
    NodeSmem& s = S[w >> 1];
    const int n = blockIdx.x * 2 + (w >> 1);

    const float4 qv = ((const float4*)(qg + (long)n * 128))[lane];

    if (half == 0) {
        s.jb[lane] = idx[n * 32 + lane];
        const float4* dg = (const float4*)(dist_g + (long)n * 1024);
#pragma unroll
        for (int it = 0; it < 4; it++) {
            int i4 = it * 32 + lane;
            float4 v = dg[i4];
            uint2 h;
            h.x = h2u(__float22half2_rn(make_float2(v.x, v.y)));
            h.y = h2u(__float22half2_rn(make_float2(v.z, v.w)));
            *(uint2*)(s.dist + (i4 >> 3) * 36 + (i4 & 7) * 4) = h;
        }
    } else {
        const float4* dg = (const float4*)(dist_g + (long)n * 1024);
#pragma unroll
        for (int it = 4; it < 8; it++) {
            int i4 = it * 32 + lane;
            float4 v = dg[i4];
            uint2 h;
            h.x = h2u(__float22half2_rn(make_float2(v.x, v.y)));
            h.y = h2u(__float22half2_rn(make_float2(v.z, v.w)));
            *(uint2*)(s.dist + (i4 >> 3) * 36 + (i4 & 7) * 4) = h;
        }
        const float4* sg = (const float4*)(seq_g + (long)n * 512);
#pragma unroll
        for (int it = 0; it < 4; it++) {
            int i4 = it * 32 + lane;
            float4 v = sg[i4];
            uint2 h;
            h.x = h2u(__float22half2_rn(make_float2(v.x, v.y)));
            h.y = h2u(__float22half2_rn(make_float2(v.z, v.w)));
            *(uint2*)(s.seq + (i4 >> 2) * 20 + (i4 & 3) * 4) = h;
        }
    }

    const int h4 = lane >> 2;
#pragma unroll 8
    for (int rr = 0; rr < 24; rr++) {
        int r = half * 24 + rr;
        float4 wv = *(const float4*)(Wk + (long)(128 + r) * 128 + lane * 4);
        float p = wv.x * qv.x + wv.y * qv.y + wv.z * qv.z + wv.w * qv.w;
        p += __shfl_xor_sync(~0u, p, 1);
        p += __shfl_xor_sync(~0u, p, 2);
        if ((lane & 3) == 0) {
            if (r < 32) s.ud_t[r * 8 + h4] = p;
            else        s.us_t[(r - 32) * 8 + h4] = p;
        }
    }
    if (half == 0) {
        float4 wv = *(const float4*)(bk + lane * 4);
        float p = wv.x * qv.x + wv.y * qv.y + wv.z * qv.z + wv.w * qv.w;
        p += __shfl_xor_sync(~0u, p, 1);
        p += __shfl_xor_sync(~0u, p, 2);
        if ((lane & 3) == 0) s.c0[h4] = p;
    }
    __syncthreads();

#pragma unroll 8
    for (int kk = 0; kk < 16; kk++) {
        int k = half * 16 + kk;
        int j = s.jb[k];
        uint2 mr = *(const uint2*)(mkh + (long)j * 128 + lane * 4);
        float2 f0 = __half22float2(*(__half2*)&mr.x);
        float2 f1 = __half22float2(*(__half2*)&mr.y);
        float p = f0.x * qv.x + f0.y * qv.y + f1.x * qv.z + f1.y * qv.w;
        p += __shfl_xor_sync(~0u, p, 1);
        p += __shfl_xor_sync(~0u, p, 2);
        if ((lane & 3) == 0) s.lgk[k * 10 + h4] = p;
    }
    __syncthreads();

    {
        ull acc01 = 0ull, acc23 = 0ull;
        const __half* drow = s.dist + lane * 36;
#pragma unroll
        for (int i = 0; i < 8; i++) {
            uint2 hv = *(const uint2*)(drow + i * 4);
            float2 f0 = __half22float2(*(__half2*)&hv.x);
            float2 f1 = __half22float2(*(__half2*)&hv.y);
            float dv[4] = {f0.x, f0.y, f1.x, f1.y};
#pragma unroll
            for (int e = 0; e < 4; e++) {
                int d = i * 4 + e;
                ull dv2 = pack2(dv[e], dv[e]);
                const ull* u = (const ull*)(s.ud_t + d * 8 + half * 4);
                acc01 = ffma2(u[0], dv2, acc01);
                acc23 = ffma2(u[1], dv2, acc23);
            }
        }
        const __half* srow = s.seq + lane * 20;
#pragma unroll
        for (int i = 0; i < 4; i++) {
            uint2 hv = *(const uint2*)(srow + i * 4);
            float2 f0 = __half22float2(*(__half2*)&hv.x);
            float2 f1 = __half22float2(*(__half2*)&hv.y);
            float sv[4] = {f0.x, f0.y, f1.x, f1.y};
#pragma unroll
            for (int e = 0; e < 4; e++) {
                int si = i * 4 + e;
                ull sv2 = pack2(sv[e], sv[e]);
                const ull* u = (const ull*)(s.us_t + si * 8 + half * 4);
                acc01 = ffma2(u[0], sv2, acc01);
                acc23 = ffma2(u[1], sv2, acc23);
            }
        }
        float2 pA = unpack2(acc01), pB = unpack2(acc23);
        float pa[4] = {pA.x, pA.y, pB.x, pB.y};
#pragma unroll
        for (int hh = 0; hh < 4; hh++) {
            int h = half * 4 + hh;
            float lg = 0.25f * (s.lgk[lane * 10 + h] + pa[hh] + s.c0[h]);
            float m = lg;
#pragma unroll
            for (int o = 16; o > 0; o >>= 1)
                m = fmaxf(m, __shfl_xor_sync(~0u, m, o));
            float e = __expf(lg - m);
            float sm = e;
#pragma unroll
            for (int o = 16; o > 0; o >>= 1)
                sm += __shfl_xor_sync(~0u, sm, o);
            s.lgk[lane * 10 + h] = e / sm;
        }
    }
    __syncthreads();

    {
        const int sidx = lane & 15;
        float4 acc = make_float4(0.f, 0.f, 0.f, 0.f);
        ull sdl2[4] = {0ull, 0ull, 0ull, 0ull};
        float ssl[4] = {0.f, 0.f, 0.f, 0.f};
#pragma unroll 4
        for (int kk = 0; kk < 16; kk++) {
            int k = half * 16 + kk;
            int j = s.jb[k];
            float a = s.lgk[k * 10 + h4];
            uint2 mr = *(const uint2*)(mvh + (long)j * 128 + lane * 4);
            float2 f0 = __half22float2(*(__half2*)&mr.x);
            float2 f1 = __half22float2(*(__half2*)&mr.y);
            acc.x += a * f0.x; acc.y += a * f0.y;
            acc.z += a * f1.x; acc.w += a * f1.y;
            float dv = __half2float(s.dist[k * 36 + lane]);
            ull dv2 = pack2(dv, dv);
            const ull* ap = (const ull*)(s.lgk + k * 10);
#pragma unroll
            for (int r = 0; r < 4; r++) sdl2[r] = ffma2(ap[r], dv2, sdl2[r]);
            float sv = __half2float(s.seq[k * 20 + sidx]);
#pragma unroll
            for (int r = 0; r < 4; r++) {
                int h2 = (lane >> 4) + 2 * r;
                ssl[r] += s.lgk[k * 10 + h2] * sv;
            }
        }
        *(float4*)(s.accp[half] + lane * 4) = acc;
#pragma unroll
        for (int r = 0; r < 4; r++) {
            float2 p = unpack2(sdl2[r]);
            s.sd[half][(2 * r) * 32 + lane] = p.x;
            s.sd[half][(2 * r + 1) * 32 + lane] = p.y;
        }
#pragma unroll
        for (int r = 0; r < 4; r++) s.ss[half][lane + 32 * r] = ssl[r];
    }
    __syncthreads();

    {
        const int i0 = half * 64 + lane * 2;
        const int h = i0 >> 4;
        float2 a0 = *(const float2*)(s.accp[0] + i0);
        float2 a1 = *(const float2*)(s.accp[1] + i0);
        float2 bb = *(const float2*)(bv + i0);
        ull o = pack2(a0.x + a1.x + bb.x, a0.y + a1.y + bb.y);
#pragma unroll 8
        for (int d = 0; d < 32; d++) {
            float sdv = s.sd[0][h * 32 + d] + s.sd[1][h * 32 + d];
            ull wv = *(const ull*)(Wv + (long)(128 + d) * 128 + i0);
            o = ffma2(wv, pack2(sdv, sdv), o);
        }
#pragma unroll 8
        for (int j2 = 0; j2 < 16; j2++) {
            int si = (h & 1) * 16 + j2 + 32 * (h >> 1);
            float ssv = s.ss[0][si] + s.ss[1][si];
            ull wv = *(const ull*)(Wv + (long)(160 + j2) * 128 + i0);
            o = ffma2(wv, pack2(ssv, ssv), o);
        }
        float2 po = unpack2(o);
        *(float2*)(att_out + (long)n * 128 + i0) = po;
    }
}

// ---------------- launch ----------------
#define TG_SMEM ((32 + 128) * KPAD * 2)            // 43,520 B
#define PERS_SMEM ((64 + 6 * 128) * KPAD * 2)      // 226,304 B (< 227 KB max)

extern "C" void kernel_launch(void* const* d_in, const int* in_sizes, int n_in,
                              void* d_out, int out_size)
{
    const float* features = (const float*)d_in[0];
    const float* distances = (const float*)d_in[1];
    const float* sequence = (const float*)d_in[2];
    const float* encoder = (const float*)d_in[3];
    const int*   idx = (const int*)d_in[4];
    const float* W1 = (const float*)d_in[5];
    const float* b1 = (const float*)d_in[6];
    const float* W2 = (const float*)d_in[7];
    const float* b2 = (const float*)d_in[8];
    const float* W3 = (const float*)d_in[9];
    const float* b3 = (const float*)d_in[10];
    const float* Wq = (const float*)d_in[11];
    const float* bq = (const float*)d_in[12];
    const float* Wk = (const float*)d_in[13];
    const float* bk = (const float*)d_in[14];
    const float* Wv = (const float*)d_in[15];
    const float* bv = (const float*)d_in[16];
    const float* Wo = (const float*)d_in[17];
    const float* bo = (const float*)d_in[18];

    float *q, *att;
    __half *mk, *mv;
    cudaGetSymbolAddress((void**)&q, g_q);
    cudaGetSymbolAddress((void**)&mk, g_mk);
    cudaGetSymbolAddress((void**)&mv, g_mv);
    cudaGetSymbolAddress((void**)&att, g_att);

    static int smem_set = 0;
    if (!smem_set) {
        cudaFuncSetAttribute(mlp_persistent,
            cudaFuncAttributeMaxDynamicSharedMemorySize, PERS_SMEM);
        smem_set = 1;
    }

    // F -> {q, h1 -> h2 -> msg -> mk, mv}: one persistent kernel,
    // weights staged once, zero intermediate DRAM traffic.
    mlp_persistent<<<128, 256, PERS_SMEM>>>(features, Wq, bq, W1, b1,
                                            W2, b2, W3, b3, encoder,
                                            Wk, Wv, q, mk, mv);
    // attention
    attn_kernel<<<N_NODES / 2, 128>>>(distances, sequence, idx,
                                      q, mk, mv, Wk, bk, Wv, bv, att);
    // out = features + att@Wo + bo
    tgemm<0,0,1,1,0><<<N_NODES / 32, 256, TG_SMEM>>>(att, Wo, bo, features,
                                                     (float*)d_out);
}

// round 15
// speedup vs baseline: 1.5963x; 1.0066x over previous
#include <cuda_runtime.h>
#include <cuda_fp16.h>

#define N_NODES 16384
#define SZ 128
#define KPAD 136   // halfs per smem row: 272B, 16B-aligned, conflict-free ldsm
typedef unsigned long long ull;
typedef unsigned int uint32;

__device__ __forceinline__ ull ffma2(ull a, ull b, ull c) {
    ull d;
    asm("fma.rn.f32x2 %0, %1, %2, %3;" : "=l"(d) : "l"(a), "l"(b), "l"(c));
    return d;
}
__device__ __forceinline__ ull pack2(float x, float y) {
    ull d;
    asm("mov.b64 %0, {%1, %2};" : "=l"(d) : "f"(x), "f"(y));
    return d;
}
__device__ __forceinline__ float2 unpack2(ull v) {
    float2 r;
    asm("mov.b64 {%0, %1}, %2;" : "=f"(r.x), "=f"(r.y) : "l"(v));
    return r;
}
__device__ __forceinline__ unsigned h2u(__half2 h) { return *(unsigned*)&h; }

__device__ __forceinline__ void ldsm_x4(uint32& r0, uint32& r1, uint32& r2,
                                        uint32& r3, uint32 addr) {
    asm volatile("ldmatrix.sync.aligned.m8n8.x4.shared.b16 {%0,%1,%2,%3}, [%4];"
                 : "=r"(r0), "=r"(r1), "=r"(r2), "=r"(r3) : "r"(addr));
}
__device__ __forceinline__ void ldsm_x2t(uint32& r0, uint32& r1, uint32 addr) {
    asm volatile("ldmatrix.sync.aligned.m8n8.x2.trans.shared.b16 {%0,%1}, [%2];"
                 : "=r"(r0), "=r"(r1) : "r"(addr));
}
__device__ __forceinline__ void mma_f16(float* c, uint32 a0, uint32 a1,
                                        uint32 a2, uint32 a3,
                                        uint32 b0, uint32 b1) {
    asm volatile(
        "mma.sync.aligned.m16n8k16.row.col.f32.f16.f16.f32 "
        "{%0,%1,%2,%3}, {%4,%5,%6,%7}, {%8,%9}, {%0,%1,%2,%3};"
        : "+f"(c[0]), "+f"(c[1]), "+f"(c[2]), "+f"(c[3])
        : "r"(a0), "r"(a1), "r"(a2), "r"(a3), "r"(b0), "r"(b1));
}

// ---------------- scratch ----------------
__device__ float  g_q[N_NODES * SZ];
__device__ __half g_mk[N_NODES * SZ];
__device__ __half g_mv[N_NODES * SZ];
__device__ __half g_att[N_NODES * SZ];

// ---------------- building blocks ----------------
// stage 128x128 fp32 weight -> fp16 smem, 512 threads
__device__ __forceinline__ void stage_W_512(const float* __restrict__ W,
                                            __half* Ws, int t) {
#pragma unroll
    for (int i = 0; i < 8; i++) {
        int idx = t + i * 512;
        int r = idx >> 5, c4 = idx & 31;
        float4 v = *(const float4*)(W + r * 128 + c4 * 4);
        uint2 pkt = make_uint2(h2u(__float22half2_rn(make_float2(v.x, v.y))),
                               h2u(__float22half2_rn(make_float2(v.z, v.w))));
        *(uint2*)(Ws + r * KPAD + c4 * 4) = pkt;
    }
}
// stage 128x128 fp32 weight -> fp16 smem, 256 threads
__device__ __forceinline__ void stage_W_256(const float* __restrict__ W,
                                            __half* Ws, int t) {
#pragma unroll
    for (int i = 0; i < 16; i++) {
        int idx = t + i * 256;
        int r = idx >> 5, c4 = idx & 31;
        float4 v = *(const float4*)(W + r * 128 + c4 * 4);
        uint2 pkt = make_uint2(h2u(__float22half2_rn(make_float2(v.x, v.y))),
                               h2u(__float22half2_rn(make_float2(v.z, v.w))));
        *(uint2*)(Ws + r * KPAD + c4 * 4) = pkt;
    }
}

__device__ __forceinline__ void tile_mma(uint32 a_base, uint32 w_base,
                                         uint32 a_off, uint32 b_krow,
                                         int nc0, float acc[4][4]) {
#pragma unroll
    for (int nt = 0; nt < 4; nt++)
#pragma unroll
        for (int c = 0; c < 4; c++) acc[nt][c] = 0.f;
#pragma unroll
    for (int ks = 0; ks < 8; ks++) {
        const int k0 = ks * 16;
        uint32 a0, a1, a2, a3;
        ldsm_x4(a0, a1, a2, a3, a_base + a_off + k0 * 2);
        uint32 baddr = w_base + ((k0 + b_krow) * KPAD + nc0) * 2;
#pragma unroll
        for (int nt = 0; nt < 4; nt++) {
            uint32 b0, b1;
            ldsm_x2t(b0, b1, baddr + nt * 16);
            mma_f16(acc[nt], a0, a1, a2, a3, b0, b1);
        }
    }
}

// epilogue -> smem fp16 tile. ADD: += addg row (fp32 gmem)
template <int RELU, int ADD>
__device__ __forceinline__ void epi_smem(float acc[4][4],
    const float* __restrict__ bias, const float* __restrict__ addg,
    long row0, __half* dst, int ar, int nc0, int lane)
{
    const int g = lane >> 2, tig = lane & 3;
#pragma unroll
    for (int nt = 0; nt < 4; nt++) {
        int col = nc0 + nt * 8 + tig * 2;
        float2 bz = *(const float2*)(bias + col);
        float2 v0 = make_float2(acc[nt][0] + bz.x, acc[nt][1] + bz.y);
        float2 v1 = make_float2(acc[nt][2] + bz.x, acc[nt][3] + bz.y);
        if (RELU) {
            v0.x = fmaxf(v0.x, 0.f); v0.y = fmaxf(v0.y, 0.f);
            v1.x = fmaxf(v1.x, 0.f); v1.y = fmaxf(v1.y, 0.f);
        }
        if (ADD) {
            float2 q0 = *(const float2*)(addg + (row0 + ar + g) * 128 + col);
            float2 q1 = *(const float2*)(addg + (row0 + ar + 8 + g) * 128 + col);
            v0.x += q0.x; v0.y += q0.y;
            v1.x += q1.x; v1.y += q1.y;
        }
        *(__half2*)(dst + (ar + g) * KPAD + col) = __float22half2_rn(v0);
        *(__half2*)(dst + (ar + 8 + g) * KPAD + col) = __float22half2_rn(v1);
    }
}

__device__ __forceinline__ void epi_gmem_h(float acc[4][4], long row0,
                                           __half* __restrict__ C,
                                           int ar, int nc0, int lane)
{
    const int g = lane >> 2, tig = lane & 3;
#pragma unroll
    for (int nt = 0; nt < 4; nt++) {
        int col = nc0 + nt * 8 + tig * 2;
        long r0 = row0 + ar + g, r1 = r0 + 8;
        *(__half2*)(C + r0 * 128 + col) =
            __float22half2_rn(make_float2(acc[nt][0], acc[nt][1]));
        *(__half2*)(C + r1 * 128 + col) =
            __float22half2_rn(make_float2(acc[nt][2], acc[nt][3]));
    }
}

__device__ __forceinline__ void epi_gmem_f(float acc[4][4],
    const float* __restrict__ bias, long row0, float* __restrict__ C,
    int ar, int nc0, int lane)
{
    const int g = lane >> 2, tig = lane & 3;
#pragma unroll
    for (int nt = 0; nt < 4; nt++) {
        int col = nc0 + nt * 8 + tig * 2;
        long r0 = row0 + ar + g, r1 = r0 + 8;
        float2 bz = *(const float2*)(bias + col);
        *(float2*)(C + r0 * 128 + col) =
            make_float2(acc[nt][0] + bz.x, acc[nt][1] + bz.y);
        *(float2*)(C + r1 * 128 + col) =
            make_float2(acc[nt][2] + bz.x, acc[nt][3] + bz.y);
    }
}

// ------- PERSISTENT MLP v2: 2 warpgroups, named barriers, weights once -----
// 148 blocks x 512 thr; wg-tile = bid*2+wg + 296*round (512 tiles, 2 rounds).
// Each wg: ONE activation buffer; q from raw F, then relu in place, then
// h1/h2/msg chain writes back into the same buffer (mma -> barrier -> epi).
#define NBAR() asm volatile("bar.sync %0, 256;" :: "r"(barid) : "memory")

__global__ __launch_bounds__(512) void mlp_persistent(
    const float* __restrict__ F,
    const float* __restrict__ Wq, const float* __restrict__ bq,
    const float* __restrict__ W1, const float* __restrict__ b1,
    const float* __restrict__ W2, const float* __restrict__ b2,
    const float* __restrict__ W3, const float* __restrict__ b3,
    const float* __restrict__ enc,
    const float* __restrict__ Wk, const float* __restrict__ Wv,
    float* __restrict__ q, __half* __restrict__ mk, __half* __restrict__ mv)
{
    extern __shared__ __half sm[];
    const int t = threadIdx.x;
    const int wg = t >> 8;              // warpgroup 0/1
    const int wt = t & 255;             // thread within wg
    __half* buf = sm + wg * 32 * KPAD;  // per-wg activation tile
    __half* WS = sm + 64 * KPAD;        // 6 x [128][KPAD]
    const int lane = t & 31;
    const int wiw = wt >> 5;            // warp in wg (0..7)
    const int mw = wiw & 1, nw = wiw >> 1;
    const int ar = mw * 16, nc0 = nw * 32;
    const int barid = 1 + wg;

    const uint32 a_base = (uint32)__cvta_generic_to_shared(buf);
    const int lrow = lane & 7, quad = lane >> 3;
    const uint32 a_off =
        ((uint32)(ar + lrow + ((quad & 1) << 3)) * KPAD + ((quad & 2) << 2)) * 2;
    const uint32 b_krow = (lane & 7) + (lane & 8);

    // ---- stage all six weights once (512 threads)
    stage_W_512(Wq, WS + 0 * 128 * KPAD, t);
    stage_W_512(W1, WS + 1 * 128 * KPAD, t);
    stage_W_512(W2, WS + 2 * 128 * KPAD, t);
    stage_W_512(W3, WS + 3 * 128 * KPAD, t);
    stage_W_512(Wk, WS + 4 * 128 * KPAD, t);
    stage_W_512(Wv, WS + 5 * 128 * KPAD, t);
    uint32 wb[6];
#pragma unroll
    for (int i = 0; i < 6; i++)
        wb[i] = (uint32)__cvta_generic_to_shared(WS + i * 128 * KPAD);
    __syncthreads();

    float acc[4][4];
#pragma unroll 1
    for (int round = 0; round < 2; round++) {
        const long tile = (long)blockIdx.x * 2 + wg + 296 * round;
        if (tile >= 512) break;          // branch uniform within wg
        const long row0 = tile * 32;

        // stage raw F -> buf (fp16)
#pragma unroll
        for (int i = 0; i < 4; i++) {
            int idx = wt + i * 256;
            int r = idx >> 5, c4 = idx & 31;
            float4 v = *(const float4*)(F + (row0 + r) * 128 + c4 * 4);
            uint2 raw = make_uint2(
                h2u(__float22half2_rn(make_float2(v.x, v.y))),
                h2u(__float22half2_rn(make_float2(v.z, v.w))));
            *(uint2*)(buf + r * KPAD + c4 * 4) = raw;
        }
        NBAR();

        // q = rawF @ Wq + bq -> gmem fp32
        tile_mma(a_base, wb[0], a_off, b_krow, nc0, acc);
        epi_gmem_f(acc, bq, row0, q, ar, nc0, lane);
        NBAR();                          // all buf reads done

        // relu in place (exact: relu commutes with fp16 rounding)
        {
            const __half2 z2 = __float2half2_rn(0.f);
#pragma unroll
            for (int i = 0; i < 2; i++) {
                int idx = wt + i * 256;
                int r = idx >> 4, c8 = idx & 15;
                __half2* p = (__half2*)(buf + r * KPAD + c8 * 8);
                p[0] = __hmax2(p[0], z2);
                p[1] = __hmax2(p[1], z2);
                p[2] = __hmax2(p[2], z2);
                p[3] = __hmax2(p[3], z2);
            }
        }
        NBAR();

        // h1 = relu(buf @ W1 + b1) -> buf
        tile_mma(a_base, wb[1], a_off, b_krow, nc0, acc);
        NBAR();
        epi_smem<1, 0>(acc, b1, nullptr, row0, buf, ar, nc0, lane);
        NBAR();

        // h2 = relu(buf @ W2 + b2) -> buf
        tile_mma(a_base, wb[2], a_off, b_krow, nc0, acc);
        NBAR();
        epi_smem<1, 0>(acc, b2, nullptr, row0, buf, ar, nc0, lane);
        NBAR();

        // msg = relu(buf @ W3 + b3) + enc -> buf
        tile_mma(a_base, wb[3], a_off, b_krow, nc0, acc);
        NBAR();
        epi_smem<1, 1>(acc, b3, enc, row0, buf, ar, nc0, lane);
        NBAR();

        // mk, mv -> gmem fp16 (read-only on buf)
        tile_mma(a_base, wb[4], a_off, b_krow, nc0, acc);
        epi_gmem_h(acc, row0, mk, ar, nc0, lane);
        tile_mma(a_base, wb[5], a_off, b_krow, nc0, acc);
        epi_gmem_h(acc, row0, mv, ar, nc0, lane);
        NBAR();                          // before next round restages buf
    }
}

// ------- out-projection: out = features + att(fp16) @ Wo + bo --------------
__global__ __launch_bounds__(256) void tgemm_out(
    const __half* __restrict__ A, const float* __restrict__ W,
    const float* __restrict__ bias, const float* __restrict__ add,
    float* __restrict__ C)
{
    extern __shared__ __half sm[];
    __half* As = sm;
    __half* Ws = sm + 32 * KPAD;
    const int t = threadIdx.x;
    const int lane = t & 31, w = t >> 5;
    const int mw = w & 1, nw = w >> 1;
    const long row0 = (long)blockIdx.x * 32;

    // stage fp16 A directly (no convert)
#pragma unroll
    for (int i = 0; i < 2; i++) {
        int idx = t + i * 256;
        int r = idx >> 4, c8 = idx & 15;
        uint4 v = *(const uint4*)(A + (row0 + r) * 128 + c8 * 8);
        *(uint4*)(As + r * KPAD + c8 * 8) = v;
    }
    stage_W_256(W, Ws, t);
    __syncthreads();

    const int ar = mw * 16, nc0 = nw * 32;
    const uint32 a_base = (uint32)__cvta_generic_to_shared(As);
    const uint32 w_base = (uint32)__cvta_generic_to_shared(Ws);
    const int lrow = lane & 7, quad = lane >> 3;
    const uint32 a_off =
        ((uint32)(ar + lrow + ((quad & 1) << 3)) * KPAD + ((quad & 2) << 2)) * 2;
    const uint32 b_krow = (lane & 7) + (lane & 8);

    float acc[4][4];
    tile_mma(a_base, w_base, a_off, b_krow, nc0, acc);

    const int g = lane >> 2, tig = lane & 3;
#pragma unroll
    for (int nt = 0; nt < 4; nt++) {
        int col = nc0 + nt * 8 + tig * 2;
        long r0 = row0 + ar + g, r1 = r0 + 8;
        float2 bz = *(const float2*)(bias + col);
        float2 a0 = *(const float2*)(add + r0 * 128 + col);
        float2 a1 = *(const float2*)(add + r1 * 128 + col);
        *(float2*)(C + r0 * 128 + col) =
            make_float2(acc[nt][0] + bz.x + a0.x, acc[nt][1] + bz.y + a0.y);
        *(float2*)(C + r1 * 128 + col) =
            make_float2(acc[nt][2] + bz.x + a1.x, acc[nt][3] + bz.y + a1.y);
    }
}

// ---------------- attention: 2 warps per node (R10-proven; fp16 output) ----
struct __align__(16) NodeSmem {
    __half dist[32 * 36];
    __half seq[32 * 20];
    float ud_t[32 * 8];
    float us_t[16 * 8];
    float c0[8];
    float lgk[32 * 10];
    float sd[2][256];
    float ss[2][128];
    float accp[2][128];
    int   jb[32];
};

__global__ __launch_bounds__(128) void attn_kernel(
    const float* __restrict__ dist_g, const float* __restrict__ seq_g,
    const int* __restrict__ idx, const float* __restrict__ qg,
    const __half* __restrict__ mkh, const __half* __restrict__ mvh,
    const float* __restrict__ Wk, const float* __restrict__ bk,
    const float* __restrict__ Wv, const float* __restrict__ bv,
    __half* __restrict__ att_out)
{
    __shared__ NodeSmem S[2];
    const int lane = threadIdx.x & 31;
    const int w = threadIdx.x >> 5;
    const int half = w & 1;
    NodeSmem& s = S[w >> 1];
    const int n = blockIdx.x * 2 + (w >> 1);

    const float4 qv = ((const float4*)(qg + (long)n * 128))[lane];

    if (half == 0) {
        s.jb[lane] = idx[n * 32 + lane];
        const float4* dg = (const float4*)(dist_g + (long)n * 1024);
#pragma unroll
        for (int it = 0; it < 4; it++) {
            int i4 = it * 32 + lane;
            float4 v = dg[i4];
            uint2 h;
            h.x = h2u(__float22half2_rn(make_float2(v.x, v.y)));
            h.y = h2u(__float22half2_rn(make_float2(v.z, v.w)));
            *(uint2*)(s.dist + (i4 >> 3) * 36 + (i4 & 7) * 4) = h;
        }
    } else {
        const float4* dg = (const float4*)(dist_g + (long)n * 1024);
#pragma unroll
        for (int it = 4; it < 8; it++) {
            int i4 = it * 32 + lane;
            float4 v = dg[i4];
            uint2 h;
            h.x = h2u(__float22half2_rn(make_float2(v.x, v.y)));
            h.y = h2u(__float22half2_rn(make_float2(v.z, v.w)));
            *(uint2*)(s.dist + (i4 >> 3) * 36 + (i4 & 7) * 4) = h;
        }
        const float4* sg = (const float4*)(seq_g + (long)n * 512);
#pragma unroll
        for (int it = 0; it < 4; it++) {
            int i4 = it * 32 + lane;
            float4 v = sg[i4];
            uint2 h;
            h.x = h2u(__float22half2_rn(make_float2(v.x, v.y)));
            h.y = h2u(__float22half2_rn(make_float2(v.z, v.w)));
            *(uint2*)(s.seq + (i4 >> 2) * 20 + (i4 & 3) * 4) = h;
        }
    }

    const int h4 = lane >> 2;
#pragma unroll 8
    for (int rr = 0; rr < 24; rr++) {
        int r = half * 24 + rr;
        float4 wv = *(const float4*)(Wk + (long)(128 + r) * 128 + lane * 4);
        float p = wv.x * qv.x + wv.y * qv.y + wv.z * qv.z + wv.w * qv.w;
        p += __shfl_xor_sync(~0u, p, 1);
        p += __shfl_xor_sync(~0u, p, 2);
        if ((lane & 3) == 0) {
            if (r < 32) s.ud_t[r * 8 + h4] = p;
            else        s.us_t[(r - 32) * 8 + h4] = p;
        }
    }
    if (half == 0) {
        float4 wv = *(const float4*)(bk + lane * 4);
        float p = wv.x * qv.x + wv.y * qv.y + wv.z * qv.z + wv.w * qv.w;
        p += __shfl_xor_sync(~0u, p, 1);
        p += __shfl_xor_sync(~0u, p, 2);
        if ((lane & 3) == 0) s.c0[h4] = p;
    }
    __syncthreads();

#pragma unroll 8
    for (int kk = 0; kk < 16; kk++) {
        int k = half * 16 + kk;
        int j = s.jb[k];
        uint2 mr = *(const uint2*)(mkh + (long)j * 128 + lane * 4);
        float2 f0 = __half22float2(*(__half2*)&mr.x);
        float2 f1 = __half22float2(*(__half2*)&mr.y);
        float p = f0.x * qv.x + f0.y * qv.y + f1.x * qv.z + f1.y * qv.w;
        p += __shfl_xor_sync(~0u, p, 1);
        p += __shfl_xor_sync(~0u, p, 2);
        if ((lane & 3) == 0) s.lgk[k * 10 + h4] = p;
    }
    __syncthreads();

    {
        ull acc01 = 0ull, acc23 = 0ull;
        const __half* drow = s.dist + lane * 36;
#pragma unroll
        for (int i = 0; i < 8; i++) {
            uint2 hv = *(const uint2*)(drow + i * 4);
            float2 f0 = __half22float2(*(__half2*)&hv.x);
            float2 f1 = __half22float2(*(__half2*)&hv.y);
            float dv[4] = {f0.x, f0.y, f1.x, f1.y};
#pragma unroll
            for (int e = 0; e < 4; e++) {
                int d = i * 4 + e;
                ull dv2 = pack2(dv[e], dv[e]);
                const ull* u = (const ull*)(s.ud_t + d * 8 + half * 4);
                acc01 = ffma2(u[0], dv2, acc01);
                acc23 = ffma2(u[1], dv2, acc23);
            }
        }
        const __half* srow = s.seq + lane * 20;
#pragma unroll
        for (int i = 0; i < 4; i++) {
            uint2 hv = *(const uint2*)(srow + i * 4);
            float2 f0 = __half22float2(*(__half2*)&hv.x);
            float2 f1 = __half22float2(*(__half2*)&hv.y);
            float sv[4] = {f0.x, f0.y, f1.x, f1.y};
#pragma unroll
            for (int e = 0; e < 4; e++) {
                int si = i * 4 + e;
                ull sv2 = pack2(sv[e], sv[e]);
                const ull* u = (const ull*)(s.us_t + si * 8 + half * 4);
                acc01 = ffma2(u[0], sv2, acc01);
                acc23 = ffma2(u[1], sv2, acc23);
            }
        }
        float2 pA = unpack2(acc01), pB = unpack2(acc23);
        float pa[4] = {pA.x, pA.y, pB.x, pB.y};
#pragma unroll
        for (int hh = 0; hh < 4; hh++) {
            int h = half * 4 + hh;
            float lg = 0.25f * (s.lgk[lane * 10 + h] + pa[hh] + s.c0[h]);
            float m = lg;
#pragma unroll
            for (int o = 16; o > 0; o >>= 1)
                m = fmaxf(m, __shfl_xor_sync(~0u, m, o));
            float e = __expf(lg - m);
            float sm = e;
#pragma unroll
            for (int o = 16; o > 0; o >>= 1)
                sm += __shfl_xor_sync(~0u, sm, o);
            s.lgk[lane * 10 + h] = e / sm;
        }
    }
    __syncthreads();

    {
        const int sidx = lane & 15;
        float4 acc = make_float4(0.f, 0.f, 0.f, 0.f);
        ull sdl2[4] = {0ull, 0ull, 0ull, 0ull};
        float ssl[4] = {0.f, 0.f, 0.f, 0.f};
#pragma unroll 4
        for (int kk = 0; kk < 16; kk++) {
            int k = half * 16 + kk;
            int j = s.jb[k];
            float a = s.lgk[k * 10 + h4];
            uint2 mr = *(const uint2*)(mvh + (long)j * 128 + lane * 4);
            float2 f0 = __half22float2(*(__half2*)&mr.x);
            float2 f1 = __half22float2(*(__half2*)&mr.y);
            acc.x += a * f0.x; acc.y += a * f0.y;
            acc.z += a * f1.x; acc.w += a * f1.y;
            float dv = __half2float(s.dist[k * 36 + lane]);
            ull dv2 = pack2(dv, dv);
            const ull* ap = (const ull*)(s.lgk + k * 10);
#pragma unroll
            for (int r = 0; r < 4; r++) sdl2[r] = ffma2(ap[r], dv2, sdl2[r]);
            float sv = __half2float(s.seq[k * 20 + sidx]);
#pragma unroll
            for (int r = 0; r < 4; r++) {
                int h2 = (lane >> 4) + 2 * r;
                ssl[r] += s.lgk[k * 10 + h2] * sv;
            }
        }
        *(float4*)(s.accp[half] + lane * 4) = acc;
#pragma unroll
        for (int r = 0; r < 4; r++) {
            float2 p = unpack2(sdl2[r]);
            s.sd[half][(2 * r) * 32 + lane] = p.x;
            s.sd[half][(2 * r + 1) * 32 + lane] = p.y;
        }
#pragma unroll
        for (int r = 0; r < 4; r++) s.ss[half][lane + 32 * r] = ssl[r];
    }
    __syncthreads();

    {
        const int i0 = half * 64 + lane * 2;
        const int h = i0 >> 4;
        float2 a0 = *(const float2*)(s.accp[0] + i0);
        float2 a1 = *(const float2*)(s.accp[1] + i0);
        float2 bb = *(const float2*)(bv + i0);
        ull o = pack2(a0.x + a1.x + bb.x, a0.y + a1.y + bb.y);
#pragma unroll 8
        for (int d = 0; d < 32; d++) {
            float sdv = s.sd[0][h * 32 + d] + s.sd[1][h * 32 + d];
            ull wv = *(const ull*)(Wv + (long)(128 + d) * 128 + i0);
            o = ffma2(wv, pack2(sdv, sdv), o);
        }
#pragma unroll 8
        for (int j2 = 0; j2 < 16; j2++) {
            int si = (h & 1) * 16 + j2 + 32 * (h >> 1);
            float ssv = s.ss[0][si] + s.ss[1][si];
            ull wv = *(const ull*)(Wv + (long)(160 + j2) * 128 + i0);
            o = ffma2(wv, pack2(ssv, ssv), o);
        }
        float2 po = unpack2(o);
        *(__half2*)(att_out + (long)n * 128 + i0) = __float22half2_rn(po);
    }
}

// ---------------- launch ----------------
#define TG_SMEM ((32 + 128) * KPAD * 2)            // 43,520 B
#define PERS_SMEM ((64 + 6 * 128) * KPAD * 2)      // 226,304 B

extern "C" void kernel_launch(void* const* d_in, const int* in_sizes, int n_in,
                              void* d_out, int out_size)
{
    const float* features = (const float*)d_in[0];
    const float* distances = (const float*)d_in[1];
    const float* sequence = (const float*)d_in[2];
    const float* encoder = (const float*)d_in[3];
    const int*   idx = (const int*)d_in[4];
    const float* W1 = (const float*)d_in[5];
    const float* b1 = (const float*)d_in[6];
    const float* W2 = (const float*)d_in[7];
    const float* b2 = (const float*)d_in[8];
    const float* W3 = (const float*)d_in[9];
    const float* b3 = (const float*)d_in[10];
    const float* Wq = (const float*)d_in[11];
    const float* bq = (const float*)d_in[12];
    const float* Wk = (const float*)d_in[13];
    const float* bk = (const float*)d_in[14];
    const float* Wv = (const float*)d_in[15];
    const float* bv = (const float*)d_in[16];
    const float* Wo = (const float*)d_in[17];
    const float* bo = (const float*)d_in[18];

    float *q;
    __half *mk, *mv, *att;
    cudaGetSymbolAddress((void**)&q, g_q);
    cudaGetSymbolAddress((void**)&mk, g_mk);
    cudaGetSymbolAddress((void**)&mv, g_mv);
    cudaGetSymbolAddress((void**)&att, g_att);

    static int smem_set = 0;
    if (!smem_set) {
        cudaFuncSetAttribute(mlp_persistent,
            cudaFuncAttributeMaxDynamicSharedMemorySize, PERS_SMEM);
        smem_set = 1;
    }

    // F -> {q, h1 -> h2 -> msg -> mk, mv}: persistent, 2 warpgroups/block
    mlp_persistent<<<148, 512, PERS_SMEM>>>(features, Wq, bq, W1, b1,
                                            W2, b2, W3, b3, encoder,
                                            Wk, Wv, q, mk, mv);
    // attention (fp16 output)
    attn_kernel<<<N_NODES / 2, 128>>>(distances, sequence, idx,
                                      q, mk, mv, Wk, bk, Wv, bv, att);
    // out = features + att@Wo + bo
    tgemm_out<<<N_NODES / 32, 256, TG_SMEM>>>(att, Wo, bo, features,
                                              (float*)d_out);
}